// round 7
// baseline (speedup 1.0000x reference)
#include <cuda_runtime.h>
#include <math_constants.h>

#define NS   5
#define NC   64
#define NB   8
#define HIN  512
#define WIN  512
#define HO   257
#define WO   257
#define NPIX (HO*WO)            // 66049
#define NGRP ((NPIX + 3) / 4)   // 16513 groups of 4 pixels
#define NSB  (NS * NB)          // 40 planes
#define NBLK 592                // exactly 4 blocks per SM on 148 SMs

// Piecewise-linear table, k-major, float2 {S1,S2}:
//   P[o](L) = max(S1 + S2*L, 0), k = #{sorted thresholds < L}
__device__ float2 g_tab[NS][65][NC];
__device__ float  g_th [NS][64];
__device__ float  g_wv [NS][4];

// ---------------------------------------------------------------------------
// Precompute, ONE launch: grid (65, 5) x 64 threads. Each block redundantly
// builds the per-scale channel meta, then fills its k-column with fp64
// masked sums split into 4 independent chains (latency /4).
// ---------------------------------------------------------------------------
__global__ void __launch_bounds__(64)
precompute_tab(
    const float* __restrict__ lp, const float* __restrict__ hp,
    const float* __restrict__ w1, const float* __restrict__ w2,
    const float* __restrict__ g1, const float* __restrict__ b1,
    const float* __restrict__ m1, const float* __restrict__ v1,
    const float* __restrict__ g2, const float* __restrict__ b2,
    const float* __restrict__ m2, const float* __restrict__ v2)
{
    const int s = blockIdx.y;
    const int k = blockIdx.x;       // 0..64
    const int c = threadIdx.x;      // 0..63

    __shared__ float  sw2[64 * 65];
    __shared__ double sAd[64], sBd[64];
    __shared__ float  sthv[64];
    __shared__ int    sidx[64];
    __shared__ int    srk [64];

    for (int i = c; i < 64 * 64; i += 64)
        sw2[(i >> 6) * 65 + (i & 63)] = w2[s * 4096 + i];

    {
        double sc1 = (double)g1[s*NC + c] / sqrt((double)v1[s*NC + c] + 1e-5);
        double sh1 = (double)b1[s*NC + c] - (double)m1[s*NC + c] * sc1;
        double A   = (double)w1[s*NC + c] * sc1;
        sAd[c] = A; sBd[c] = sh1;
        sthv[c] = (A != 0.0) ? (float)(-sh1 / A) : CUDART_INF_F;
        sidx[c] = c;
    }
    __syncthreads();

    for (int ksz = 2; ksz <= 64; ksz <<= 1) {
        for (int j = ksz >> 1; j > 0; j >>= 1) {
            int ixj = c ^ j;
            if (ixj > c) {
                float a = sthv[c], bb = sthv[ixj];
                int   ia = sidx[c], ib = sidx[ixj];
                bool  up = ((c & ksz) == 0);
                if (up ? (a > bb) : (a < bb)) {
                    sthv[c] = bb; sthv[ixj] = a;
                    sidx[c] = ib; sidx[ixj] = ia;
                }
            }
            __syncthreads();
        }
    }

    srk[sidx[c]] = c;
    if (k == 0) {
        g_th[s][c] = sthv[c];
        if (c == 0) {
            g_wv[s][0] = lp[s*2]; g_wv[s][1] = lp[s*2+1];
            g_wv[s][2] = hp[s*2]; g_wv[s][3] = hp[s*2+1];
        }
    }
    __syncthreads();

    const int o = c;
    double sc2 = (double)g2[s*NC + o] / sqrt((double)v2[s*NC + o] + 1e-5);
    double sh2 = (double)b2[s*NC + o] - (double)m2[s*NC + o] * sc2;

    // 4 independent accumulator chains
    double s1a = 0.0, s2a = 0.0, s1b = 0.0, s2b = 0.0;
    double s1c = 0.0, s2c = 0.0, s1d = 0.0, s2d = 0.0;
    #pragma unroll 4
    for (int cc = 0; cc < 64; cc += 4) {
        #define ACC(CI, S1, S2)                                          \
        {   double a = sAd[CI], bb = sBd[CI];                            \
            bool act = (a > 0.0) ? (srk[CI] < k)                         \
                     : (a < 0.0) ? (srk[CI] >= k)                        \
                                 : (bb > 0.0);                           \
            if (act) {                                                   \
                double w = (double)sw2[o*65 + (CI)];                     \
                S1 += w * bb;  S2 += w * a;                              \
            }                                                            \
        }
        ACC(cc + 0, s1a, s2a)
        ACC(cc + 1, s1b, s2b)
        ACC(cc + 2, s1c, s2c)
        ACC(cc + 3, s1d, s2d)
        #undef ACC
    }
    double s1 = (s1a + s1b) + (s1c + s1d);
    double s2 = (s2a + s2b) + (s2c + s2d);
    g_tab[s][k][o] = make_float2((float)(sc2*s1 + sh2), (float)(sc2*s2));
}

// ---------------------------------------------------------------------------
// Main kernel: 1D grid of 592 blocks (exactly 4/SM), each owning a
// contiguous chunk of the global (plane x group) space. Inner loop is the
// measured-best R3 code: thread owns 4 consecutive pixels; STG.128 via
// per-plane shift d = o & 3 with a 7-slot shfl halo window.
// ---------------------------------------------------------------------------
__global__ void __launch_bounds__(256)
dwt_pwl_kernel(const float* __restrict__ x, float* __restrict__ out)
{
    __shared__ float2 stab[65 * 65];
    __shared__ float  sth[64];

    const long long totalG = (long long)NGRP * NSB;         // 660520
    const long long per    = (totalG + NBLK - 1) / NBLK;     // 1116
    long long pos  = (long long)blockIdx.x * per;
    long long gend = pos + per;
    if (gend > totalG) gend = totalG;

    const int lane = threadIdx.x & 31;

    while (pos < gend) {
        const int sb = (int)(pos / NGRP);
        const long long planeBase = (long long)sb * NGRP;
        long long segEnd = planeBase + NGRP;
        if (segEnd > gend) segEnd = gend;

        const int s = sb / NB;
        const int b = sb - s * NB;

        // (re)load the per-scale table
        __syncthreads();
        {
            const float2* gt = &g_tab[s][0][0];
            for (int i = threadIdx.x; i < 65 * 64; i += 256) {
                int kk = i >> 6, oo = i & 63;
                stab[kk * 65 + oo] = gt[i];
            }
            if (threadIdx.x < 64) sth[threadIdx.x] = g_th[s][threadIdx.x];
        }
        __syncthreads();

        const float lp0 = g_wv[s][0], lp1 = g_wv[s][1];
        const float hp0 = g_wv[s][2], hp1 = g_wv[s][3];

        const float* __restrict__ xb = x + (size_t)b * HIN * WIN;
        float* __restrict__ outL = out + (size_t)sb * NPIX;
        float* __restrict__ outH = out + (size_t)(NSB + sb) * NPIX;
        float* __restrict__ outP = out + (size_t)2*NSB*NPIX
                                       + (size_t)sb * NC * NPIX;

        auto pixLHK = [&](int pix, float& L, float& H, int& k) {
            L = 0.f; H = 0.f;
            if (pix >= 0 && pix < NPIX) {
                unsigned up = (unsigned)pix;
                int i = up / WO;
                int j = up - i * WO;
                int r0 = 2*i - 1, r1 = 2*i;
                int c0 = 2*j - 1, c1 = 2*j;
                float x00 = (r0 >= 0  && c0 >= 0 ) ? xb[r0*WIN + c0] : 0.f;
                float x01 = (r0 >= 0  && c1 < WIN) ? xb[r0*WIN + c1] : 0.f;
                float x10 = (r1 < HIN && c0 >= 0 ) ? xb[r1*WIN + c0] : 0.f;
                float x11 = (r1 < HIN && c1 < WIN) ? xb[r1*WIN + c1] : 0.f;
                L = lp0*(lp0*x00 + lp1*x01) + lp1*(lp0*x10 + lp1*x11);
                H = hp0*(hp0*x00 + hp1*x01) + hp1*(hp0*x10 + hp1*x11);
            }
            int kk = (sth[31]       < L) ? 32 : 0;
            kk += (sth[kk + 15] < L) ? 16 : 0;
            kk += (sth[kk +  7] < L) ?  8 : 0;
            kk += (sth[kk +  3] < L) ?  4 : 0;
            kk += (sth[kk +  1] < L) ?  2 : 0;
            kk += (sth[kk     ] < L) ?  1 : 0;
            k = kk;
        };

        for (long long base = pos; base < segEnd; base += 256) {
            const long long gg = base + threadIdx.x;
            const int g    = (int)(gg - planeBase);   // may exceed NGRP for tails
            const int pix0 = 4 * g;
            const bool valid = (gg < segEnd);

            float Ls[7], Hs[7]; int ks[7];
            pixLHK(pix0 + 0, Ls[3], Hs[3], ks[3]);
            pixLHK(pix0 + 1, Ls[4], Hs[4], ks[4]);
            pixLHK(pix0 + 2, Ls[5], Hs[5], ks[5]);
            pixLHK(pix0 + 3, Ls[6], Hs[6], ks[6]);

            // halo via shfl; lane 0 recomputes
            Ls[0] = __shfl_up_sync(0xffffffffu, Ls[4], 1);
            Ls[1] = __shfl_up_sync(0xffffffffu, Ls[5], 1);
            Ls[2] = __shfl_up_sync(0xffffffffu, Ls[6], 1);
            Hs[0] = __shfl_up_sync(0xffffffffu, Hs[4], 1);
            Hs[1] = __shfl_up_sync(0xffffffffu, Hs[5], 1);
            Hs[2] = __shfl_up_sync(0xffffffffu, Hs[6], 1);
            ks[0] = __shfl_up_sync(0xffffffffu, ks[4], 1);
            ks[1] = __shfl_up_sync(0xffffffffu, ks[5], 1);
            ks[2] = __shfl_up_sync(0xffffffffu, ks[6], 1);
            if (lane == 0) {
                pixLHK(pix0 - 3, Ls[0], Hs[0], ks[0]);
                pixLHK(pix0 - 2, Ls[1], Hs[1], ks[1]);
                pixLHK(pix0 - 1, Ls[2], Hs[2], ks[2]);
            }

            if (!valid) continue;

            const bool edge = (g == 0) || (g == NGRP - 1);

            if (!edge) {
                float* bp = outP + pix0;
                #pragma unroll
                for (int q = 0; q < 16; q++) {
                    const int o0 = 4 * q;
                    {   // d=0: slots 3..6
                        float2 f0 = stab[ks[3]*65 + o0], f1 = stab[ks[4]*65 + o0];
                        float2 f2 = stab[ks[5]*65 + o0], f3 = stab[ks[6]*65 + o0];
                        float4 v = make_float4(fmaxf(fmaf(f0.y, Ls[3], f0.x), 0.f),
                                               fmaxf(fmaf(f1.y, Ls[4], f1.x), 0.f),
                                               fmaxf(fmaf(f2.y, Ls[5], f2.x), 0.f),
                                               fmaxf(fmaf(f3.y, Ls[6], f3.x), 0.f));
                        *reinterpret_cast<float4*>(bp) = v;
                    }
                    {   // d=1: slots 2..5
                        float2 f0 = stab[ks[2]*65 + o0+1], f1 = stab[ks[3]*65 + o0+1];
                        float2 f2 = stab[ks[4]*65 + o0+1], f3 = stab[ks[5]*65 + o0+1];
                        float4 v = make_float4(fmaxf(fmaf(f0.y, Ls[2], f0.x), 0.f),
                                               fmaxf(fmaf(f1.y, Ls[3], f1.x), 0.f),
                                               fmaxf(fmaf(f2.y, Ls[4], f2.x), 0.f),
                                               fmaxf(fmaf(f3.y, Ls[5], f3.x), 0.f));
                        *reinterpret_cast<float4*>(bp + (NPIX - 1)) = v;
                    }
                    {   // d=2: slots 1..4
                        float2 f0 = stab[ks[1]*65 + o0+2], f1 = stab[ks[2]*65 + o0+2];
                        float2 f2 = stab[ks[3]*65 + o0+2], f3 = stab[ks[4]*65 + o0+2];
                        float4 v = make_float4(fmaxf(fmaf(f0.y, Ls[1], f0.x), 0.f),
                                               fmaxf(fmaf(f1.y, Ls[2], f1.x), 0.f),
                                               fmaxf(fmaf(f2.y, Ls[3], f2.x), 0.f),
                                               fmaxf(fmaf(f3.y, Ls[4], f3.x), 0.f));
                        *reinterpret_cast<float4*>(bp + (2*NPIX - 2)) = v;
                    }
                    {   // d=3: slots 0..3
                        float2 f0 = stab[ks[0]*65 + o0+3], f1 = stab[ks[1]*65 + o0+3];
                        float2 f2 = stab[ks[2]*65 + o0+3], f3 = stab[ks[3]*65 + o0+3];
                        float4 v = make_float4(fmaxf(fmaf(f0.y, Ls[0], f0.x), 0.f),
                                               fmaxf(fmaf(f1.y, Ls[1], f1.x), 0.f),
                                               fmaxf(fmaf(f2.y, Ls[2], f2.x), 0.f),
                                               fmaxf(fmaf(f3.y, Ls[3], f3.x), 0.f));
                        *reinterpret_cast<float4*>(bp + (3*NPIX - 3)) = v;
                    }
                    bp += (size_t)4 * NPIX;
                }

                switch (sb & 3) {
                case 0:
                    *reinterpret_cast<float4*>(outL + pix0) =
                        make_float4(Ls[3], Ls[4], Ls[5], Ls[6]);
                    *reinterpret_cast<float4*>(outH + pix0) =
                        make_float4(Hs[3], Hs[4], Hs[5], Hs[6]);
                    break;
                case 1:
                    *reinterpret_cast<float4*>(outL + pix0 - 1) =
                        make_float4(Ls[2], Ls[3], Ls[4], Ls[5]);
                    *reinterpret_cast<float4*>(outH + pix0 - 1) =
                        make_float4(Hs[2], Hs[3], Hs[4], Hs[5]);
                    break;
                case 2:
                    *reinterpret_cast<float4*>(outL + pix0 - 2) =
                        make_float4(Ls[1], Ls[2], Ls[3], Ls[4]);
                    *reinterpret_cast<float4*>(outH + pix0 - 2) =
                        make_float4(Hs[1], Hs[2], Hs[3], Hs[4]);
                    break;
                default:
                    *reinterpret_cast<float4*>(outL + pix0 - 3) =
                        make_float4(Ls[0], Ls[1], Ls[2], Ls[3]);
                    *reinterpret_cast<float4*>(outH + pix0 - 3) =
                        make_float4(Hs[0], Hs[1], Hs[2], Hs[3]);
                    break;
                }
            } else {
                #pragma unroll 4
                for (int o = 0; o < 64; o++) {
                    const int d = o & 3;
                    #pragma unroll
                    for (int e = 0; e < 4; e++) {
                        int pix = pix0 - d + e;
                        if (pix >= 0 && pix < NPIX) {
                            float2 f = stab[ks[3 - d + e] * 65 + o];
                            outP[(size_t)o * NPIX + pix] =
                                fmaxf(fmaf(f.y, Ls[3 - d + e], f.x), 0.f);
                        }
                    }
                }
                switch (sb & 3) {
                #define EDGE_LH(D)                                          \
                    { _Pragma("unroll")                                     \
                      for (int e = 0; e < 4; e++) {                         \
                          int pix = pix0 - (D) + e;                         \
                          if (pix >= 0 && pix < NPIX) {                     \
                              outL[pix] = Ls[3 - (D) + e];                  \
                              outH[pix] = Hs[3 - (D) + e];                  \
                          }                                                 \
                      } }
                case 0:  EDGE_LH(0) break;
                case 1:  EDGE_LH(1) break;
                case 2:  EDGE_LH(2) break;
                default: EDGE_LH(3) break;
                #undef EDGE_LH
                }
            }
        }
        pos = segEnd;
    }
}

// ---------------------------------------------------------------------------
extern "C" void kernel_launch(void* const* d_in, const int* in_sizes, int n_in,
                              void* d_out, int out_size)
{
    const float* x  = (const float*)d_in[0];
    const float* lp = (const float*)d_in[1];
    const float* hp = (const float*)d_in[2];
    const float* w1 = (const float*)d_in[3];
    const float* w2 = (const float*)d_in[4];
    const float* g1 = (const float*)d_in[5];
    const float* b1 = (const float*)d_in[6];
    const float* m1 = (const float*)d_in[7];
    const float* v1 = (const float*)d_in[8];
    const float* g2 = (const float*)d_in[9];
    const float* b2 = (const float*)d_in[10];
    const float* m2 = (const float*)d_in[11];
    const float* v2 = (const float*)d_in[12];
    float* out = (float*)d_out;

    precompute_tab<<<dim3(65, NS), 64>>>(lp, hp, w1, w2, g1, b1, m1, v1,
                                         g2, b2, m2, v2);

    dwt_pwl_kernel<<<NBLK, 256>>>(x, out);
}

// round 8
// speedup vs baseline: 1.0173x; 1.0173x over previous
#include <cuda_runtime.h>
#include <math_constants.h>

#define NS   5
#define NC   64
#define NB   8
#define HIN  512
#define WIN  512
#define HO   257
#define WO   257
#define NPIX (HO*WO)            // 66049
#define NGRP ((NPIX + 3) / 4)   // 16513 groups of 4 pixels

// Piecewise-linear table, k-major, float2 {S1,S2}:
//   P[o](L) = max(S1 + S2*L, 0), k = #{sorted thresholds < L}
__device__ float2 g_tab[NS][65][NC];
__device__ float  g_th [NS][64];
__device__ float  g_wv [NS][4];

// ---------------------------------------------------------------------------
// Precompute: grid (17, 5) x 256 threads. Each block covers 4 k-columns
// (k = 4*bx + tid>>6). 8 warps stage w2; threads <64 build channel meta and
// bitonic-sort thresholds; then every thread fills entry (s, k, o=tid&63)
// with 4-way-split fp64 masked sums (same grouping as R7 -> same rel_err).
// ---------------------------------------------------------------------------
__global__ void __launch_bounds__(256)
precompute_tab(
    const float* __restrict__ lp, const float* __restrict__ hp,
    const float* __restrict__ w1, const float* __restrict__ w2,
    const float* __restrict__ g1, const float* __restrict__ b1,
    const float* __restrict__ m1, const float* __restrict__ v1,
    const float* __restrict__ g2, const float* __restrict__ b2,
    const float* __restrict__ m2, const float* __restrict__ v2)
{
    const int s   = blockIdx.y;
    const int tid = threadIdx.x;
    const int k   = blockIdx.x * 4 + (tid >> 6);   // 0..67 (guard <= 64)
    const int o   = tid & 63;

    __shared__ float  sw2[64 * 65];
    __shared__ double sAd[64], sBd[64];
    __shared__ float  sthv[64];
    __shared__ int    sidx[64];
    __shared__ int    srk [64];

    // stage w2 with all 8 warps (coalesced)
    for (int i = tid; i < 64 * 64; i += 256)
        sw2[(i >> 6) * 65 + (i & 63)] = w2[s * 4096 + i];

    if (tid < 64) {
        const int c = tid;
        double sc1 = (double)g1[s*NC + c] / sqrt((double)v1[s*NC + c] + 1e-5);
        double sh1 = (double)b1[s*NC + c] - (double)m1[s*NC + c] * sc1;
        double A   = (double)w1[s*NC + c] * sc1;
        sAd[c] = A; sBd[c] = sh1;
        sthv[c] = (A != 0.0) ? (float)(-sh1 / A) : CUDART_INF_F;
        sidx[c] = c;
    }
    __syncthreads();

    // bitonic sort of 64 (key sthv, payload sidx); all threads hit the syncs
    for (int ksz = 2; ksz <= 64; ksz <<= 1) {
        for (int j = ksz >> 1; j > 0; j >>= 1) {
            if (tid < 64) {
                int ixj = tid ^ j;
                if (ixj > tid) {
                    float a = sthv[tid], bb = sthv[ixj];
                    int   ia = sidx[tid], ib = sidx[ixj];
                    bool  up = ((tid & ksz) == 0);
                    if (up ? (a > bb) : (a < bb)) {
                        sthv[tid] = bb; sthv[ixj] = a;
                        sidx[tid] = ib; sidx[ixj] = ia;
                    }
                }
            }
            __syncthreads();
        }
    }

    if (tid < 64) {
        srk[sidx[tid]] = tid;
        if (blockIdx.x == 0) {
            g_th[s][tid] = sthv[tid];
            if (tid == 0) {
                g_wv[s][0] = lp[s*2]; g_wv[s][1] = lp[s*2+1];
                g_wv[s][2] = hp[s*2]; g_wv[s][3] = hp[s*2+1];
            }
        }
    }
    __syncthreads();

    if (k > 64) return;

    double sc2 = (double)g2[s*NC + o] / sqrt((double)v2[s*NC + o] + 1e-5);
    double sh2 = (double)b2[s*NC + o] - (double)m2[s*NC + o] * sc2;

    // 4 independent accumulator chains (same grouping as R7)
    double s1a = 0.0, s2a = 0.0, s1b = 0.0, s2b = 0.0;
    double s1c = 0.0, s2c = 0.0, s1d = 0.0, s2d = 0.0;
    #pragma unroll 4
    for (int cc = 0; cc < 64; cc += 4) {
        #define ACC(CI, S1, S2)                                          \
        {   double a = sAd[CI], bb = sBd[CI];                            \
            bool act = (a > 0.0) ? (srk[CI] < k)                         \
                     : (a < 0.0) ? (srk[CI] >= k)                        \
                                 : (bb > 0.0);                           \
            if (act) {                                                   \
                double w = (double)sw2[o*65 + (CI)];                     \
                S1 += w * bb;  S2 += w * a;                              \
            }                                                            \
        }
        ACC(cc + 0, s1a, s2a)
        ACC(cc + 1, s1b, s2b)
        ACC(cc + 2, s1c, s2c)
        ACC(cc + 3, s1d, s2d)
        #undef ACC
    }
    double s1 = (s1a + s1b) + (s1c + s1d);
    double s2 = (s2a + s2b) + (s2c + s2d);
    g_tab[s][k][o] = make_float2((float)(sc2*s1 + sh2), (float)(sc2*s2));
}

// ---------------------------------------------------------------------------
// Main kernel (R6 verbatim — measured 155.5 us): grid (15, 40), thread owns
// 4 consecutive pixels; STG.128 everywhere via per-plane shift d = o & 3
// with a 7-slot (3 halo + 4 own) register window filled via shfl.
// ---------------------------------------------------------------------------
__global__ void __launch_bounds__(256)
dwt_pwl_kernel(const float* __restrict__ x, float* __restrict__ out)
{
    __shared__ float2 stab[65 * 65];   // idx = k*65 + o  (padded stride)
    __shared__ float  sth[64];

    const int sb = blockIdx.y;          // 0..39
    const int s  = sb / NB;
    const int b  = sb - s * NB;

    const float2* gt = &g_tab[s][0][0];
    for (int i = threadIdx.x; i < 65 * 64; i += 256) {
        int k = i >> 6, o = i & 63;
        stab[k * 65 + o] = gt[i];
    }
    if (threadIdx.x < 64) sth[threadIdx.x] = g_th[s][threadIdx.x];
    __syncthreads();

    const float lp0 = g_wv[s][0], lp1 = g_wv[s][1];
    const float hp0 = g_wv[s][2], hp1 = g_wv[s][3];

    const float* __restrict__ xb = x + (size_t)b * HIN * WIN;
    float* __restrict__ outL = out + (size_t)sb * NPIX;
    float* __restrict__ outH = out + (size_t)(NS*NB + sb) * NPIX;
    float* __restrict__ outP = out + (size_t)2*NS*NB*NPIX + (size_t)sb * NC * NPIX;

    const int lane = threadIdx.x & 31;
    const int gstride = gridDim.x * blockDim.x;

    // compute L, Hc, rank k for one pixel (fully guarded, incl. bottom row)
    auto pixLHK = [&](int pix, float& L, float& H, int& k) {
        L = 0.f; H = 0.f;
        if (pix >= 0 && pix < NPIX) {
            unsigned up = (unsigned)pix;
            int i = up / WO;
            int j = up - i * WO;
            int r0 = 2*i - 1, r1 = 2*i;
            int c0 = 2*j - 1, c1 = 2*j;
            float x00 = (r0 >= 0  && c0 >= 0 ) ? xb[r0*WIN + c0] : 0.f;
            float x01 = (r0 >= 0  && c1 < WIN) ? xb[r0*WIN + c1] : 0.f;
            float x10 = (r1 < HIN && c0 >= 0 ) ? xb[r1*WIN + c0] : 0.f;
            float x11 = (r1 < HIN && c1 < WIN) ? xb[r1*WIN + c1] : 0.f;
            L = lp0*(lp0*x00 + lp1*x01) + lp1*(lp0*x10 + lp1*x11);
            H = hp0*(hp0*x00 + hp1*x01) + hp1*(hp0*x10 + hp1*x11);
        }
        int kk = (sth[31]       < L) ? 32 : 0;
        kk += (sth[kk + 15] < L) ? 16 : 0;
        kk += (sth[kk +  7] < L) ?  8 : 0;
        kk += (sth[kk +  3] < L) ?  4 : 0;
        kk += (sth[kk +  1] < L) ?  2 : 0;
        kk += (sth[kk     ] < L) ?  1 : 0;
        k = kk;
    };

    for (int gw = blockIdx.x * 256 + (int)(threadIdx.x & ~31u); gw < NGRP;
         gw += gstride)
    {
        const int g = gw + lane;
        const int pix0 = 4 * g;

        float Ls[7], Hs[7]; int ks[7];
        pixLHK(pix0 + 0, Ls[3], Hs[3], ks[3]);
        pixLHK(pix0 + 1, Ls[4], Hs[4], ks[4]);
        pixLHK(pix0 + 2, Ls[5], Hs[5], ks[5]);
        pixLHK(pix0 + 3, Ls[6], Hs[6], ks[6]);

        // halo (previous group's pixels 1..3) via shfl; lane 0 recomputes
        Ls[0] = __shfl_up_sync(0xffffffffu, Ls[4], 1);
        Ls[1] = __shfl_up_sync(0xffffffffu, Ls[5], 1);
        Ls[2] = __shfl_up_sync(0xffffffffu, Ls[6], 1);
        Hs[0] = __shfl_up_sync(0xffffffffu, Hs[4], 1);
        Hs[1] = __shfl_up_sync(0xffffffffu, Hs[5], 1);
        Hs[2] = __shfl_up_sync(0xffffffffu, Hs[6], 1);
        ks[0] = __shfl_up_sync(0xffffffffu, ks[4], 1);
        ks[1] = __shfl_up_sync(0xffffffffu, ks[5], 1);
        ks[2] = __shfl_up_sync(0xffffffffu, ks[6], 1);
        if (lane == 0) {
            pixLHK(pix0 - 3, Ls[0], Hs[0], ks[0]);
            pixLHK(pix0 - 2, Ls[1], Hs[1], ks[1]);
            pixLHK(pix0 - 1, Ls[2], Hs[2], ks[2]);
        }

        if (g >= NGRP) continue;

        const bool edge = (g == 0) || (g == NGRP - 1);

        if (!edge) {
            // ---- P planes: 16 quads of 4 channels, one STG.128 each ----
            float* bp = outP + pix0;
            #pragma unroll
            for (int q = 0; q < 16; q++) {
                const int o0 = 4 * q;
                {   // o0, d=0: slots 3..6, addr +0
                    float2 f0 = stab[ks[3]*65 + o0], f1 = stab[ks[4]*65 + o0];
                    float2 f2 = stab[ks[5]*65 + o0], f3 = stab[ks[6]*65 + o0];
                    float4 v = make_float4(fmaxf(fmaf(f0.y, Ls[3], f0.x), 0.f),
                                           fmaxf(fmaf(f1.y, Ls[4], f1.x), 0.f),
                                           fmaxf(fmaf(f2.y, Ls[5], f2.x), 0.f),
                                           fmaxf(fmaf(f3.y, Ls[6], f3.x), 0.f));
                    *reinterpret_cast<float4*>(bp) = v;
                }
                {   // o0+1, d=1: slots 2..5, addr +NPIX-1
                    float2 f0 = stab[ks[2]*65 + o0+1], f1 = stab[ks[3]*65 + o0+1];
                    float2 f2 = stab[ks[4]*65 + o0+1], f3 = stab[ks[5]*65 + o0+1];
                    float4 v = make_float4(fmaxf(fmaf(f0.y, Ls[2], f0.x), 0.f),
                                           fmaxf(fmaf(f1.y, Ls[3], f1.x), 0.f),
                                           fmaxf(fmaf(f2.y, Ls[4], f2.x), 0.f),
                                           fmaxf(fmaf(f3.y, Ls[5], f3.x), 0.f));
                    *reinterpret_cast<float4*>(bp + (NPIX - 1)) = v;
                }
                {   // o0+2, d=2: slots 1..4, addr +2*NPIX-2
                    float2 f0 = stab[ks[1]*65 + o0+2], f1 = stab[ks[2]*65 + o0+2];
                    float2 f2 = stab[ks[3]*65 + o0+2], f3 = stab[ks[4]*65 + o0+2];
                    float4 v = make_float4(fmaxf(fmaf(f0.y, Ls[1], f0.x), 0.f),
                                           fmaxf(fmaf(f1.y, Ls[2], f1.x), 0.f),
                                           fmaxf(fmaf(f2.y, Ls[3], f2.x), 0.f),
                                           fmaxf(fmaf(f3.y, Ls[4], f3.x), 0.f));
                    *reinterpret_cast<float4*>(bp + (2*NPIX - 2)) = v;
                }
                {   // o0+3, d=3: slots 0..3, addr +3*NPIX-3
                    float2 f0 = stab[ks[0]*65 + o0+3], f1 = stab[ks[1]*65 + o0+3];
                    float2 f2 = stab[ks[2]*65 + o0+3], f3 = stab[ks[3]*65 + o0+3];
                    float4 v = make_float4(fmaxf(fmaf(f0.y, Ls[0], f0.x), 0.f),
                                           fmaxf(fmaf(f1.y, Ls[1], f1.x), 0.f),
                                           fmaxf(fmaf(f2.y, Ls[2], f2.x), 0.f),
                                           fmaxf(fmaf(f3.y, Ls[3], f3.x), 0.f));
                    *reinterpret_cast<float4*>(bp + (3*NPIX - 3)) = v;
                }
                bp += (size_t)4 * NPIX;
            }

            // ---- L / Hc planes: runtime shift (uniform per block) ----
            switch (sb & 3) {
            case 0:
                *reinterpret_cast<float4*>(outL + pix0) =
                    make_float4(Ls[3], Ls[4], Ls[5], Ls[6]);
                *reinterpret_cast<float4*>(outH + pix0) =
                    make_float4(Hs[3], Hs[4], Hs[5], Hs[6]);
                break;
            case 1:
                *reinterpret_cast<float4*>(outL + pix0 - 1) =
                    make_float4(Ls[2], Ls[3], Ls[4], Ls[5]);
                *reinterpret_cast<float4*>(outH + pix0 - 1) =
                    make_float4(Hs[2], Hs[3], Hs[4], Hs[5]);
                break;
            case 2:
                *reinterpret_cast<float4*>(outL + pix0 - 2) =
                    make_float4(Ls[1], Ls[2], Ls[3], Ls[4]);
                *reinterpret_cast<float4*>(outH + pix0 - 2) =
                    make_float4(Hs[1], Hs[2], Hs[3], Hs[4]);
                break;
            default:
                *reinterpret_cast<float4*>(outL + pix0 - 3) =
                    make_float4(Ls[0], Ls[1], Ls[2], Ls[3]);
                *reinterpret_cast<float4*>(outH + pix0 - 3) =
                    make_float4(Hs[0], Hs[1], Hs[2], Hs[3]);
                break;
            }
        } else {
            // ---- edge groups (first/last of plane): masked scalar stores ----
            #pragma unroll 4
            for (int o = 0; o < 64; o++) {
                const int d = o & 3;
                #pragma unroll
                for (int e = 0; e < 4; e++) {
                    int pix = pix0 - d + e;
                    if (pix >= 0 && pix < NPIX) {
                        float2 f = stab[ks[3 - d + e] * 65 + o];
                        outP[(size_t)o * NPIX + pix] =
                            fmaxf(fmaf(f.y, Ls[3 - d + e], f.x), 0.f);
                    }
                }
            }
            switch (sb & 3) {
            #define EDGE_LH(D)                                              \
                { _Pragma("unroll")                                         \
                  for (int e = 0; e < 4; e++) {                             \
                      int pix = pix0 - (D) + e;                             \
                      if (pix >= 0 && pix < NPIX) {                         \
                          outL[pix] = Ls[3 - (D) + e];                      \
                          outH[pix] = Hs[3 - (D) + e];                      \
                      }                                                     \
                  } }
            case 0:  EDGE_LH(0) break;
            case 1:  EDGE_LH(1) break;
            case 2:  EDGE_LH(2) break;
            default: EDGE_LH(3) break;
            #undef EDGE_LH
            }
        }
    }
}

// ---------------------------------------------------------------------------
extern "C" void kernel_launch(void* const* d_in, const int* in_sizes, int n_in,
                              void* d_out, int out_size)
{
    const float* x  = (const float*)d_in[0];
    const float* lp = (const float*)d_in[1];
    const float* hp = (const float*)d_in[2];
    const float* w1 = (const float*)d_in[3];
    const float* w2 = (const float*)d_in[4];
    const float* g1 = (const float*)d_in[5];
    const float* b1 = (const float*)d_in[6];
    const float* m1 = (const float*)d_in[7];
    const float* v1 = (const float*)d_in[8];
    const float* g2 = (const float*)d_in[9];
    const float* b2 = (const float*)d_in[10];
    const float* m2 = (const float*)d_in[11];
    const float* v2 = (const float*)d_in[12];
    float* out = (float*)d_out;

    precompute_tab<<<dim3(17, NS), 256>>>(lp, hp, w1, w2, g1, b1, m1, v1,
                                          g2, b2, m2, v2);

    dim3 grid(15, NS * NB);   // 600 blocks (R6 config, measured 155.5 us)
    dwt_pwl_kernel<<<grid, 256>>>(x, out);
}

// round 9
// speedup vs baseline: 1.0534x; 1.0355x over previous
#include <cuda_runtime.h>
#include <math_constants.h>

#define NS   5
#define NC   64
#define NB   8
#define HIN  512
#define WIN  512
#define HO   257
#define WO   257
#define NPIX (HO*WO)            // 66049
#define NGRP ((NPIX + 3) / 4)   // 16513 groups of 4 pixels

// Piecewise-linear table, k-major, float2 {S1,S2}:
//   P[o](L) = max(S1 + S2*L, 0), k = #{sorted thresholds < L}
__device__ float2 g_tab[NS][65][NC];
__device__ float  g_th [NS][64];
__device__ float  g_wv [NS][4];

// ---------------------------------------------------------------------------
// Precompute (R6 verbatim — measured-best gap): grid (65, 5) x 64 threads.
// Each block redundantly builds per-scale channel meta, then fills its
// k-column with fp64 masked sums split into 4 independent chains.
// ---------------------------------------------------------------------------
__global__ void __launch_bounds__(64)
precompute_tab(
    const float* __restrict__ lp, const float* __restrict__ hp,
    const float* __restrict__ w1, const float* __restrict__ w2,
    const float* __restrict__ g1, const float* __restrict__ b1,
    const float* __restrict__ m1, const float* __restrict__ v1,
    const float* __restrict__ g2, const float* __restrict__ b2,
    const float* __restrict__ m2, const float* __restrict__ v2)
{
    const int s = blockIdx.y;
    const int k = blockIdx.x;       // 0..64
    const int c = threadIdx.x;      // 0..63

    __shared__ float  sw2[64 * 65];
    __shared__ double sAd[64], sBd[64];
    __shared__ float  sthv[64];
    __shared__ int    sidx[64];
    __shared__ int    srk [64];

    for (int i = c; i < 64 * 64; i += 64)
        sw2[(i >> 6) * 65 + (i & 63)] = w2[s * 4096 + i];

    {
        double sc1 = (double)g1[s*NC + c] / sqrt((double)v1[s*NC + c] + 1e-5);
        double sh1 = (double)b1[s*NC + c] - (double)m1[s*NC + c] * sc1;
        double A   = (double)w1[s*NC + c] * sc1;
        sAd[c] = A; sBd[c] = sh1;
        sthv[c] = (A != 0.0) ? (float)(-sh1 / A) : CUDART_INF_F;
        sidx[c] = c;
    }
    __syncthreads();

    for (int ksz = 2; ksz <= 64; ksz <<= 1) {
        for (int j = ksz >> 1; j > 0; j >>= 1) {
            int ixj = c ^ j;
            if (ixj > c) {
                float a = sthv[c], bb = sthv[ixj];
                int   ia = sidx[c], ib = sidx[ixj];
                bool  up = ((c & ksz) == 0);
                if (up ? (a > bb) : (a < bb)) {
                    sthv[c] = bb; sthv[ixj] = a;
                    sidx[c] = ib; sidx[ixj] = ia;
                }
            }
            __syncthreads();
        }
    }

    srk[sidx[c]] = c;
    if (k == 0) {
        g_th[s][c] = sthv[c];
        if (c == 0) {
            g_wv[s][0] = lp[s*2]; g_wv[s][1] = lp[s*2+1];
            g_wv[s][2] = hp[s*2]; g_wv[s][3] = hp[s*2+1];
        }
    }
    __syncthreads();

    const int o = c;
    double sc2 = (double)g2[s*NC + o] / sqrt((double)v2[s*NC + o] + 1e-5);
    double sh2 = (double)b2[s*NC + o] - (double)m2[s*NC + o] * sc2;

    double s1a = 0.0, s2a = 0.0, s1b = 0.0, s2b = 0.0;
    double s1c = 0.0, s2c = 0.0, s1d = 0.0, s2d = 0.0;
    #pragma unroll 4
    for (int cc = 0; cc < 64; cc += 4) {
        #define ACC(CI, S1, S2)                                          \
        {   double a = sAd[CI], bb = sBd[CI];                            \
            bool act = (a > 0.0) ? (srk[CI] < k)                         \
                     : (a < 0.0) ? (srk[CI] >= k)                        \
                                 : (bb > 0.0);                           \
            if (act) {                                                   \
                double w = (double)sw2[o*65 + (CI)];                     \
                S1 += w * bb;  S2 += w * a;                              \
            }                                                            \
        }
        ACC(cc + 0, s1a, s2a)
        ACC(cc + 1, s1b, s2b)
        ACC(cc + 2, s1c, s2c)
        ACC(cc + 3, s1d, s2d)
        #undef ACC
    }
    double s1 = (s1a + s1b) + (s1c + s1d);
    double s2 = (s2a + s2b) + (s2c + s2d);
    g_tab[s][k][o] = make_float2((float)(sc2*s1 + sh2), (float)(sc2*s2));
}

// ---------------------------------------------------------------------------
// Main kernel: grid (30, 40) [R3 best], thread owns 4 consecutive pixels;
// STG.128 everywhere via per-plane shift d = o & 3 with a 7-slot shfl halo
// window. Aligned-float2 input fast path (proven in R5) for interior rows.
// ---------------------------------------------------------------------------
__global__ void __launch_bounds__(256)
dwt_pwl_kernel(const float* __restrict__ x, float* __restrict__ out)
{
    __shared__ float2 stab[65 * 65];   // idx = k*65 + o  (padded stride)
    __shared__ float  sth[64];

    const int sb = blockIdx.y;          // 0..39
    const int s  = sb / NB;
    const int b  = sb - s * NB;

    const float2* gt = &g_tab[s][0][0];
    for (int i = threadIdx.x; i < 65 * 64; i += 256) {
        int k = i >> 6, o = i & 63;
        stab[k * 65 + o] = gt[i];
    }
    if (threadIdx.x < 64) sth[threadIdx.x] = g_th[s][threadIdx.x];
    __syncthreads();

    const float lp0 = g_wv[s][0], lp1 = g_wv[s][1];
    const float hp0 = g_wv[s][2], hp1 = g_wv[s][3];

    const float* __restrict__ xb = x + (size_t)b * HIN * WIN;
    float* __restrict__ outL = out + (size_t)sb * NPIX;
    float* __restrict__ outH = out + (size_t)(NS*NB + sb) * NPIX;
    float* __restrict__ outP = out + (size_t)2*NS*NB*NPIX + (size_t)sb * NC * NPIX;

    const int lane = threadIdx.x & 31;
    const int gstride = gridDim.x * blockDim.x;

    auto rankOf = [&](float L) -> int {
        int kk = (sth[31]       < L) ? 32 : 0;
        kk += (sth[kk + 15] < L) ? 16 : 0;
        kk += (sth[kk +  7] < L) ?  8 : 0;
        kk += (sth[kk +  3] < L) ?  4 : 0;
        kk += (sth[kk +  1] < L) ?  2 : 0;
        kk += (sth[kk     ] < L) ?  1 : 0;
        return kk;
    };

    // scalar fallback: L, Hc, rank for one pixel (fully guarded)
    auto pixLHK = [&](int pix, float& L, float& H, int& k) {
        L = 0.f; H = 0.f;
        if (pix >= 0 && pix < NPIX) {
            unsigned up = (unsigned)pix;
            int i = up / WO;
            int j = up - i * WO;
            int r0 = 2*i - 1, r1 = 2*i;
            int c0 = 2*j - 1, c1 = 2*j;
            float x00 = (r0 >= 0  && c0 >= 0 ) ? xb[r0*WIN + c0] : 0.f;
            float x01 = (r0 >= 0  && c1 < WIN) ? xb[r0*WIN + c1] : 0.f;
            float x10 = (r1 < HIN && c0 >= 0 ) ? xb[r1*WIN + c0] : 0.f;
            float x11 = (r1 < HIN && c1 < WIN) ? xb[r1*WIN + c1] : 0.f;
            L = lp0*(lp0*x00 + lp1*x01) + lp1*(lp0*x10 + lp1*x11);
            H = hp0*(hp0*x00 + hp1*x01) + hp1*(hp0*x10 + hp1*x11);
        }
        k = rankOf(L);
    };

    for (int gw = blockIdx.x * 256 + (int)(threadIdx.x & ~31u); gw < NGRP;
         gw += gstride)
    {
        const int g = gw + lane;
        const int pix0 = 4 * g;

        float Ls[7], Hs[7]; int ks[7];

        // ---- own 4 pixels: aligned-float2 fast path (same row, interior) ----
        const int irow = pix0 / WO;
        const int j0   = pix0 - irow * WO;
        if (g < NGRP && j0 <= 252 && irow < 256) {
            const int r0 = 2*irow - 1, r1 = 2*irow;
            const bool h0 = (r0 >= 0);
            const float* p0 = xb + r0 * WIN;
            const float* p1 = xb + r1 * WIN;
            const int cb = 2*j0 - 2;
            float2 t0[5], t1[5];
            #pragma unroll
            for (int e = 0; e < 5; e++) {
                const int cc = cb + 2*e;
                const bool okc = (cc >= 0);
                t0[e] = (h0 && okc) ? *reinterpret_cast<const float2*>(p0 + cc)
                                    : make_float2(0.f, 0.f);
                t1[e] = (okc)      ? *reinterpret_cast<const float2*>(p1 + cc)
                                    : make_float2(0.f, 0.f);
            }
            #pragma unroll
            for (int e = 0; e < 4; e++) {
                const float x00 = t0[e].y, x01 = t0[e+1].x;
                const float x10 = t1[e].y, x11 = t1[e+1].x;
                Ls[3+e] = lp0*(lp0*x00 + lp1*x01) + lp1*(lp0*x10 + lp1*x11);
                Hs[3+e] = hp0*(hp0*x00 + hp1*x01) + hp1*(hp0*x10 + hp1*x11);
                ks[3+e] = rankOf(Ls[3+e]);
            }
        } else {
            pixLHK(pix0 + 0, Ls[3], Hs[3], ks[3]);
            pixLHK(pix0 + 1, Ls[4], Hs[4], ks[4]);
            pixLHK(pix0 + 2, Ls[5], Hs[5], ks[5]);
            pixLHK(pix0 + 3, Ls[6], Hs[6], ks[6]);
        }

        // halo (previous group's pixels 1..3) via shfl; lane 0 recomputes
        Ls[0] = __shfl_up_sync(0xffffffffu, Ls[4], 1);
        Ls[1] = __shfl_up_sync(0xffffffffu, Ls[5], 1);
        Ls[2] = __shfl_up_sync(0xffffffffu, Ls[6], 1);
        Hs[0] = __shfl_up_sync(0xffffffffu, Hs[4], 1);
        Hs[1] = __shfl_up_sync(0xffffffffu, Hs[5], 1);
        Hs[2] = __shfl_up_sync(0xffffffffu, Hs[6], 1);
        ks[0] = __shfl_up_sync(0xffffffffu, ks[4], 1);
        ks[1] = __shfl_up_sync(0xffffffffu, ks[5], 1);
        ks[2] = __shfl_up_sync(0xffffffffu, ks[6], 1);
        if (lane == 0) {
            pixLHK(pix0 - 3, Ls[0], Hs[0], ks[0]);
            pixLHK(pix0 - 2, Ls[1], Hs[1], ks[1]);
            pixLHK(pix0 - 1, Ls[2], Hs[2], ks[2]);
        }

        if (g >= NGRP) continue;

        const bool edge = (g == 0) || (g == NGRP - 1);

        if (!edge) {
            // ---- P planes: 16 quads of 4 channels, one STG.128 each ----
            float* bp = outP + pix0;
            #pragma unroll
            for (int q = 0; q < 16; q++) {
                const int o0 = 4 * q;
                {   // o0, d=0: slots 3..6, addr +0
                    float2 f0 = stab[ks[3]*65 + o0], f1 = stab[ks[4]*65 + o0];
                    float2 f2 = stab[ks[5]*65 + o0], f3 = stab[ks[6]*65 + o0];
                    float4 v = make_float4(fmaxf(fmaf(f0.y, Ls[3], f0.x), 0.f),
                                           fmaxf(fmaf(f1.y, Ls[4], f1.x), 0.f),
                                           fmaxf(fmaf(f2.y, Ls[5], f2.x), 0.f),
                                           fmaxf(fmaf(f3.y, Ls[6], f3.x), 0.f));
                    *reinterpret_cast<float4*>(bp) = v;
                }
                {   // o0+1, d=1: slots 2..5, addr +NPIX-1
                    float2 f0 = stab[ks[2]*65 + o0+1], f1 = stab[ks[3]*65 + o0+1];
                    float2 f2 = stab[ks[4]*65 + o0+1], f3 = stab[ks[5]*65 + o0+1];
                    float4 v = make_float4(fmaxf(fmaf(f0.y, Ls[2], f0.x), 0.f),
                                           fmaxf(fmaf(f1.y, Ls[3], f1.x), 0.f),
                                           fmaxf(fmaf(f2.y, Ls[4], f2.x), 0.f),
                                           fmaxf(fmaf(f3.y, Ls[5], f3.x), 0.f));
                    *reinterpret_cast<float4*>(bp + (NPIX - 1)) = v;
                }
                {   // o0+2, d=2: slots 1..4, addr +2*NPIX-2
                    float2 f0 = stab[ks[1]*65 + o0+2], f1 = stab[ks[2]*65 + o0+2];
                    float2 f2 = stab[ks[3]*65 + o0+2], f3 = stab[ks[4]*65 + o0+2];
                    float4 v = make_float4(fmaxf(fmaf(f0.y, Ls[1], f0.x), 0.f),
                                           fmaxf(fmaf(f1.y, Ls[2], f1.x), 0.f),
                                           fmaxf(fmaf(f2.y, Ls[3], f2.x), 0.f),
                                           fmaxf(fmaf(f3.y, Ls[4], f3.x), 0.f));
                    *reinterpret_cast<float4*>(bp + (2*NPIX - 2)) = v;
                }
                {   // o0+3, d=3: slots 0..3, addr +3*NPIX-3
                    float2 f0 = stab[ks[0]*65 + o0+3], f1 = stab[ks[1]*65 + o0+3];
                    float2 f2 = stab[ks[2]*65 + o0+3], f3 = stab[ks[3]*65 + o0+3];
                    float4 v = make_float4(fmaxf(fmaf(f0.y, Ls[0], f0.x), 0.f),
                                           fmaxf(fmaf(f1.y, Ls[1], f1.x), 0.f),
                                           fmaxf(fmaf(f2.y, Ls[2], f2.x), 0.f),
                                           fmaxf(fmaf(f3.y, Ls[3], f3.x), 0.f));
                    *reinterpret_cast<float4*>(bp + (3*NPIX - 3)) = v;
                }
                bp += (size_t)4 * NPIX;
            }

            // ---- L / Hc planes: runtime shift (uniform per block) ----
            switch (sb & 3) {
            case 0:
                *reinterpret_cast<float4*>(outL + pix0) =
                    make_float4(Ls[3], Ls[4], Ls[5], Ls[6]);
                *reinterpret_cast<float4*>(outH + pix0) =
                    make_float4(Hs[3], Hs[4], Hs[5], Hs[6]);
                break;
            case 1:
                *reinterpret_cast<float4*>(outL + pix0 - 1) =
                    make_float4(Ls[2], Ls[3], Ls[4], Ls[5]);
                *reinterpret_cast<float4*>(outH + pix0 - 1) =
                    make_float4(Hs[2], Hs[3], Hs[4], Hs[5]);
                break;
            case 2:
                *reinterpret_cast<float4*>(outL + pix0 - 2) =
                    make_float4(Ls[1], Ls[2], Ls[3], Ls[4]);
                *reinterpret_cast<float4*>(outH + pix0 - 2) =
                    make_float4(Hs[1], Hs[2], Hs[3], Hs[4]);
                break;
            default:
                *reinterpret_cast<float4*>(outL + pix0 - 3) =
                    make_float4(Ls[0], Ls[1], Ls[2], Ls[3]);
                *reinterpret_cast<float4*>(outH + pix0 - 3) =
                    make_float4(Hs[0], Hs[1], Hs[2], Hs[3]);
                break;
            }
        } else {
            // ---- edge groups (first/last of plane): masked scalar stores ----
            #pragma unroll 4
            for (int o = 0; o < 64; o++) {
                const int d = o & 3;
                #pragma unroll
                for (int e = 0; e < 4; e++) {
                    int pix = pix0 - d + e;
                    if (pix >= 0 && pix < NPIX) {
                        float2 f = stab[ks[3 - d + e] * 65 + o];
                        outP[(size_t)o * NPIX + pix] =
                            fmaxf(fmaf(f.y, Ls[3 - d + e], f.x), 0.f);
                    }
                }
            }
            switch (sb & 3) {
            #define EDGE_LH(D)                                              \
                { _Pragma("unroll")                                         \
                  for (int e = 0; e < 4; e++) {                             \
                      int pix = pix0 - (D) + e;                             \
                      if (pix >= 0 && pix < NPIX) {                         \
                          outL[pix] = Ls[3 - (D) + e];                      \
                          outH[pix] = Hs[3 - (D) + e];                      \
                      }                                                     \
                  } }
            case 0:  EDGE_LH(0) break;
            case 1:  EDGE_LH(1) break;
            case 2:  EDGE_LH(2) break;
            default: EDGE_LH(3) break;
            #undef EDGE_LH
            }
        }
    }
}

// ---------------------------------------------------------------------------
extern "C" void kernel_launch(void* const* d_in, const int* in_sizes, int n_in,
                              void* d_out, int out_size)
{
    const float* x  = (const float*)d_in[0];
    const float* lp = (const float*)d_in[1];
    const float* hp = (const float*)d_in[2];
    const float* w1 = (const float*)d_in[3];
    const float* w2 = (const float*)d_in[4];
    const float* g1 = (const float*)d_in[5];
    const float* b1 = (const float*)d_in[6];
    const float* m1 = (const float*)d_in[7];
    const float* v1 = (const float*)d_in[8];
    const float* g2 = (const float*)d_in[9];
    const float* b2 = (const float*)d_in[10];
    const float* m2 = (const float*)d_in[11];
    const float* v2 = (const float*)d_in[12];
    float* out = (float*)d_out;

    precompute_tab<<<dim3(65, NS), 64>>>(lp, hp, w1, w2, g1, b1, m1, v1,
                                         g2, b2, m2, v2);

    dim3 grid(30, NS * NB);   // 1200 blocks (R3 main config, measured 152.7 us)
    dwt_pwl_kernel<<<grid, 256>>>(x, out);
}

// round 10
// speedup vs baseline: 1.1432x; 1.0853x over previous
#include <cuda_runtime.h>
#include <math_constants.h>

#define NS   5
#define NC   64
#define NB   8
#define HIN  512
#define WIN  512
#define HO   257
#define WO   257
#define NPIX (HO*WO)            // 66049
#define NGRP ((NPIX + 3) / 4)   // 16513 groups of 4 pixels

// Piecewise-linear table, k-major, float2 {S1,S2}:
//   P[o](L) = max(S1 + S2*L, 0), k = #{sorted thresholds < L}
__device__ float2 g_tab[NS][65][NC];
__device__ float  g_th [NS][64];
__device__ float  g_wv [NS][4];

// ---------------------------------------------------------------------------
// Precompute: grid (65, 5) x 64 threads. fp64 channel meta + bitonic sort
// (identical k-bucketing to previous rounds); w2 staged via LDG.128; table
// sums in fp32 with 4 independent split accumulators (proven in R4).
// ---------------------------------------------------------------------------
__global__ void __launch_bounds__(64)
precompute_tab(
    const float* __restrict__ lp, const float* __restrict__ hp,
    const float* __restrict__ w1, const float* __restrict__ w2,
    const float* __restrict__ g1, const float* __restrict__ b1,
    const float* __restrict__ m1, const float* __restrict__ v1,
    const float* __restrict__ g2, const float* __restrict__ b2,
    const float* __restrict__ m2, const float* __restrict__ v2)
{
    const int s = blockIdx.y;
    const int k = blockIdx.x;       // 0..64
    const int c = threadIdx.x;      // 0..63

    __shared__ float  sw2[64 * 65];   // padded stride 65: conflict-free columns
    __shared__ float  sAf[64], sBf[64];
    __shared__ float  sthv[64];
    __shared__ int    sidx[64];
    __shared__ int    srk [64];
    __shared__ signed char scls[64];  // 1: A>0, 2: A<0, 3: A==0 && B>0, 0: dead

    // stage w2 with vector loads: 16 LDG.128 per thread
    {
        const float4* w2v = reinterpret_cast<const float4*>(w2) + s * 1024;
        #pragma unroll
        for (int t = 0; t < 16; t++) {
            const int i   = c + t * 64;       // float4 index 0..1023
            const float4 v = w2v[i];
            const int row = i >> 4;           // 16 float4 per row
            const int col = (i & 15) * 4;
            float* dst = &sw2[row * 65 + col];
            dst[0] = v.x; dst[1] = v.y; dst[2] = v.z; dst[3] = v.w;
        }
    }

    // per-channel meta in fp64 (k-bucketing identical to prior rounds)
    {
        double sc1 = (double)g1[s*NC + c] / sqrt((double)v1[s*NC + c] + 1e-5);
        double sh1 = (double)b1[s*NC + c] - (double)m1[s*NC + c] * sc1;
        double A   = (double)w1[s*NC + c] * sc1;
        sAf[c]  = (float)A;
        sBf[c]  = (float)sh1;
        scls[c] = (A > 0.0) ? 1 : (A < 0.0) ? 2 : (sh1 > 0.0) ? 3 : 0;
        sthv[c] = (A != 0.0) ? (float)(-sh1 / A) : CUDART_INF_F;
        sidx[c] = c;
    }
    __syncthreads();

    // bitonic sort of 64 (key sthv, payload sidx)
    for (int ksz = 2; ksz <= 64; ksz <<= 1) {
        for (int j = ksz >> 1; j > 0; j >>= 1) {
            int ixj = c ^ j;
            if (ixj > c) {
                float a = sthv[c], bb = sthv[ixj];
                int   ia = sidx[c], ib = sidx[ixj];
                bool  up = ((c & ksz) == 0);
                if (up ? (a > bb) : (a < bb)) {
                    sthv[c] = bb; sthv[ixj] = a;
                    sidx[c] = ib; sidx[ixj] = ia;
                }
            }
            __syncthreads();
        }
    }

    srk[sidx[c]] = c;
    if (k == 0) {
        g_th[s][c] = sthv[c];
        if (c == 0) {
            g_wv[s][0] = lp[s*2]; g_wv[s][1] = lp[s*2+1];
            g_wv[s][2] = hp[s*2]; g_wv[s][3] = hp[s*2+1];
        }
    }
    __syncthreads();

    // entry (s, k, o = c): fp32 masked sums, 4 independent chains
    const int o = c;
    const double sc2 = (double)g2[s*NC + o] / sqrt((double)v2[s*NC + o] + 1e-5);
    const double sh2 = (double)b2[s*NC + o] - (double)m2[s*NC + o] * sc2;

    float s1a = 0.f, s2a = 0.f, s1b = 0.f, s2b = 0.f;
    float s1c = 0.f, s2c = 0.f, s1d = 0.f, s2d = 0.f;
    #pragma unroll
    for (int cc = 0; cc < 64; cc += 4) {
        #define ACC(CI, S1, S2)                                          \
        {   const int cl = scls[CI];                                     \
            const bool act = (cl == 1) ? (srk[CI] < k)                   \
                           : (cl == 2) ? (srk[CI] >= k)                  \
                                       : (cl == 3);                      \
            if (act) {                                                   \
                const float w = sw2[o*65 + (CI)];                        \
                S1 = fmaf(w, sBf[CI], S1);                               \
                S2 = fmaf(w, sAf[CI], S2);                               \
            }                                                            \
        }
        ACC(cc + 0, s1a, s2a)
        ACC(cc + 1, s1b, s2b)
        ACC(cc + 2, s1c, s2c)
        ACC(cc + 3, s1d, s2d)
        #undef ACC
    }
    const double s1 = (double)((s1a + s1b) + (s1c + s1d));
    const double s2 = (double)((s2a + s2b) + (s2c + s2d));
    g_tab[s][k][o] = make_float2((float)(sc2*s1 + sh2), (float)(sc2*s2));
}

// ---------------------------------------------------------------------------
// Main kernel (R8 verbatim — measured 152.7/154.1/155.5 across rounds):
// grid (15, 40), thread owns 4 consecutive pixels; STG.128 everywhere via
// per-plane shift d = o & 3 with a 7-slot (3 halo + 4 own) shfl window.
// ---------------------------------------------------------------------------
__global__ void __launch_bounds__(256)
dwt_pwl_kernel(const float* __restrict__ x, float* __restrict__ out)
{
    __shared__ float2 stab[65 * 65];   // idx = k*65 + o  (padded stride)
    __shared__ float  sth[64];

    const int sb = blockIdx.y;          // 0..39
    const int s  = sb / NB;
    const int b  = sb - s * NB;

    const float2* gt = &g_tab[s][0][0];
    for (int i = threadIdx.x; i < 65 * 64; i += 256) {
        int k = i >> 6, o = i & 63;
        stab[k * 65 + o] = gt[i];
    }
    if (threadIdx.x < 64) sth[threadIdx.x] = g_th[s][threadIdx.x];
    __syncthreads();

    const float lp0 = g_wv[s][0], lp1 = g_wv[s][1];
    const float hp0 = g_wv[s][2], hp1 = g_wv[s][3];

    const float* __restrict__ xb = x + (size_t)b * HIN * WIN;
    float* __restrict__ outL = out + (size_t)sb * NPIX;
    float* __restrict__ outH = out + (size_t)(NS*NB + sb) * NPIX;
    float* __restrict__ outP = out + (size_t)2*NS*NB*NPIX + (size_t)sb * NC * NPIX;

    const int lane = threadIdx.x & 31;
    const int gstride = gridDim.x * blockDim.x;

    // compute L, Hc, rank k for one pixel (fully guarded, incl. bottom row)
    auto pixLHK = [&](int pix, float& L, float& H, int& k) {
        L = 0.f; H = 0.f;
        if (pix >= 0 && pix < NPIX) {
            unsigned up = (unsigned)pix;
            int i = up / WO;
            int j = up - i * WO;
            int r0 = 2*i - 1, r1 = 2*i;
            int c0 = 2*j - 1, c1 = 2*j;
            float x00 = (r0 >= 0  && c0 >= 0 ) ? xb[r0*WIN + c0] : 0.f;
            float x01 = (r0 >= 0  && c1 < WIN) ? xb[r0*WIN + c1] : 0.f;
            float x10 = (r1 < HIN && c0 >= 0 ) ? xb[r1*WIN + c0] : 0.f;
            float x11 = (r1 < HIN && c1 < WIN) ? xb[r1*WIN + c1] : 0.f;
            L = lp0*(lp0*x00 + lp1*x01) + lp1*(lp0*x10 + lp1*x11);
            H = hp0*(hp0*x00 + hp1*x01) + hp1*(hp0*x10 + hp1*x11);
        }
        int kk = (sth[31]       < L) ? 32 : 0;
        kk += (sth[kk + 15] < L) ? 16 : 0;
        kk += (sth[kk +  7] < L) ?  8 : 0;
        kk += (sth[kk +  3] < L) ?  4 : 0;
        kk += (sth[kk +  1] < L) ?  2 : 0;
        kk += (sth[kk     ] < L) ?  1 : 0;
        k = kk;
    };

    for (int gw = blockIdx.x * 256 + (int)(threadIdx.x & ~31u); gw < NGRP;
         gw += gstride)
    {
        const int g = gw + lane;
        const int pix0 = 4 * g;

        float Ls[7], Hs[7]; int ks[7];
        pixLHK(pix0 + 0, Ls[3], Hs[3], ks[3]);
        pixLHK(pix0 + 1, Ls[4], Hs[4], ks[4]);
        pixLHK(pix0 + 2, Ls[5], Hs[5], ks[5]);
        pixLHK(pix0 + 3, Ls[6], Hs[6], ks[6]);

        // halo (previous group's pixels 1..3) via shfl; lane 0 recomputes
        Ls[0] = __shfl_up_sync(0xffffffffu, Ls[4], 1);
        Ls[1] = __shfl_up_sync(0xffffffffu, Ls[5], 1);
        Ls[2] = __shfl_up_sync(0xffffffffu, Ls[6], 1);
        Hs[0] = __shfl_up_sync(0xffffffffu, Hs[4], 1);
        Hs[1] = __shfl_up_sync(0xffffffffu, Hs[5], 1);
        Hs[2] = __shfl_up_sync(0xffffffffu, Hs[6], 1);
        ks[0] = __shfl_up_sync(0xffffffffu, ks[4], 1);
        ks[1] = __shfl_up_sync(0xffffffffu, ks[5], 1);
        ks[2] = __shfl_up_sync(0xffffffffu, ks[6], 1);
        if (lane == 0) {
            pixLHK(pix0 - 3, Ls[0], Hs[0], ks[0]);
            pixLHK(pix0 - 2, Ls[1], Hs[1], ks[1]);
            pixLHK(pix0 - 1, Ls[2], Hs[2], ks[2]);
        }

        if (g >= NGRP) continue;

        const bool edge = (g == 0) || (g == NGRP - 1);

        if (!edge) {
            // ---- P planes: 16 quads of 4 channels, one STG.128 each ----
            float* bp = outP + pix0;
            #pragma unroll
            for (int q = 0; q < 16; q++) {
                const int o0 = 4 * q;
                {   // o0, d=0: slots 3..6, addr +0
                    float2 f0 = stab[ks[3]*65 + o0], f1 = stab[ks[4]*65 + o0];
                    float2 f2 = stab[ks[5]*65 + o0], f3 = stab[ks[6]*65 + o0];
                    float4 v = make_float4(fmaxf(fmaf(f0.y, Ls[3], f0.x), 0.f),
                                           fmaxf(fmaf(f1.y, Ls[4], f1.x), 0.f),
                                           fmaxf(fmaf(f2.y, Ls[5], f2.x), 0.f),
                                           fmaxf(fmaf(f3.y, Ls[6], f3.x), 0.f));
                    *reinterpret_cast<float4*>(bp) = v;
                }
                {   // o0+1, d=1: slots 2..5, addr +NPIX-1
                    float2 f0 = stab[ks[2]*65 + o0+1], f1 = stab[ks[3]*65 + o0+1];
                    float2 f2 = stab[ks[4]*65 + o0+1], f3 = stab[ks[5]*65 + o0+1];
                    float4 v = make_float4(fmaxf(fmaf(f0.y, Ls[2], f0.x), 0.f),
                                           fmaxf(fmaf(f1.y, Ls[3], f1.x), 0.f),
                                           fmaxf(fmaf(f2.y, Ls[4], f2.x), 0.f),
                                           fmaxf(fmaf(f3.y, Ls[5], f3.x), 0.f));
                    *reinterpret_cast<float4*>(bp + (NPIX - 1)) = v;
                }
                {   // o0+2, d=2: slots 1..4, addr +2*NPIX-2
                    float2 f0 = stab[ks[1]*65 + o0+2], f1 = stab[ks[2]*65 + o0+2];
                    float2 f2 = stab[ks[3]*65 + o0+2], f3 = stab[ks[4]*65 + o0+2];
                    float4 v = make_float4(fmaxf(fmaf(f0.y, Ls[1], f0.x), 0.f),
                                           fmaxf(fmaf(f1.y, Ls[2], f1.x), 0.f),
                                           fmaxf(fmaf(f2.y, Ls[3], f2.x), 0.f),
                                           fmaxf(fmaf(f3.y, Ls[4], f3.x), 0.f));
                    *reinterpret_cast<float4*>(bp + (2*NPIX - 2)) = v;
                }
                {   // o0+3, d=3: slots 0..3, addr +3*NPIX-3
                    float2 f0 = stab[ks[0]*65 + o0+3], f1 = stab[ks[1]*65 + o0+3];
                    float2 f2 = stab[ks[2]*65 + o0+3], f3 = stab[ks[3]*65 + o0+3];
                    float4 v = make_float4(fmaxf(fmaf(f0.y, Ls[0], f0.x), 0.f),
                                           fmaxf(fmaf(f1.y, Ls[1], f1.x), 0.f),
                                           fmaxf(fmaf(f2.y, Ls[2], f2.x), 0.f),
                                           fmaxf(fmaf(f3.y, Ls[3], f3.x), 0.f));
                    *reinterpret_cast<float4*>(bp + (3*NPIX - 3)) = v;
                }
                bp += (size_t)4 * NPIX;
            }

            // ---- L / Hc planes: runtime shift (uniform per block) ----
            switch (sb & 3) {
            case 0:
                *reinterpret_cast<float4*>(outL + pix0) =
                    make_float4(Ls[3], Ls[4], Ls[5], Ls[6]);
                *reinterpret_cast<float4*>(outH + pix0) =
                    make_float4(Hs[3], Hs[4], Hs[5], Hs[6]);
                break;
            case 1:
                *reinterpret_cast<float4*>(outL + pix0 - 1) =
                    make_float4(Ls[2], Ls[3], Ls[4], Ls[5]);
                *reinterpret_cast<float4*>(outH + pix0 - 1) =
                    make_float4(Hs[2], Hs[3], Hs[4], Hs[5]);
                break;
            case 2:
                *reinterpret_cast<float4*>(outL + pix0 - 2) =
                    make_float4(Ls[1], Ls[2], Ls[3], Ls[4]);
                *reinterpret_cast<float4*>(outH + pix0 - 2) =
                    make_float4(Hs[1], Hs[2], Hs[3], Hs[4]);
                break;
            default:
                *reinterpret_cast<float4*>(outL + pix0 - 3) =
                    make_float4(Ls[0], Ls[1], Ls[2], Ls[3]);
                *reinterpret_cast<float4*>(outH + pix0 - 3) =
                    make_float4(Hs[0], Hs[1], Hs[2], Hs[3]);
                break;
            }
        } else {
            // ---- edge groups (first/last of plane): masked scalar stores ----
            #pragma unroll 4
            for (int o = 0; o < 64; o++) {
                const int d = o & 3;
                #pragma unroll
                for (int e = 0; e < 4; e++) {
                    int pix = pix0 - d + e;
                    if (pix >= 0 && pix < NPIX) {
                        float2 f = stab[ks[3 - d + e] * 65 + o];
                        outP[(size_t)o * NPIX + pix] =
                            fmaxf(fmaf(f.y, Ls[3 - d + e], f.x), 0.f);
                    }
                }
            }
            switch (sb & 3) {
            #define EDGE_LH(D)                                              \
                { _Pragma("unroll")                                         \
                  for (int e = 0; e < 4; e++) {                             \
                      int pix = pix0 - (D) + e;                             \
                      if (pix >= 0 && pix < NPIX) {                         \
                          outL[pix] = Ls[3 - (D) + e];                      \
                          outH[pix] = Hs[3 - (D) + e];                      \
                      }                                                     \
                  } }
            case 0:  EDGE_LH(0) break;
            case 1:  EDGE_LH(1) break;
            case 2:  EDGE_LH(2) break;
            default: EDGE_LH(3) break;
            #undef EDGE_LH
            }
        }
    }
}

// ---------------------------------------------------------------------------
extern "C" void kernel_launch(void* const* d_in, const int* in_sizes, int n_in,
                              void* d_out, int out_size)
{
    const float* x  = (const float*)d_in[0];
    const float* lp = (const float*)d_in[1];
    const float* hp = (const float*)d_in[2];
    const float* w1 = (const float*)d_in[3];
    const float* w2 = (const float*)d_in[4];
    const float* g1 = (const float*)d_in[5];
    const float* b1 = (const float*)d_in[6];
    const float* m1 = (const float*)d_in[7];
    const float* v1 = (const float*)d_in[8];
    const float* g2 = (const float*)d_in[9];
    const float* b2 = (const float*)d_in[10];
    const float* m2 = (const float*)d_in[11];
    const float* v2 = (const float*)d_in[12];
    float* out = (float*)d_out;

    precompute_tab<<<dim3(65, NS), 64>>>(lp, hp, w1, w2, g1, b1, m1, v1,
                                         g2, b2, m2, v2);

    dim3 grid(15, NS * NB);   // 600 blocks (best-measured main config)
    dwt_pwl_kernel<<<grid, 256>>>(x, out);
}

// round 11
// speedup vs baseline: 1.1834x; 1.0351x over previous
#include <cuda_runtime.h>
#include <math_constants.h>

#define NS   5
#define NC   64
#define NB   8
#define HIN  512
#define WIN  512
#define HO   257
#define WO   257
#define NPIX (HO*WO)            // 66049
#define NGRP ((NPIX + 3) / 4)   // 16513 groups of 4 pixels

// Piecewise-linear table, k-major, float2 {S1,S2}:
//   P[o](L) = max(S1 + S2*L, 0), k = #{sorted thresholds < L}
__device__ float2 g_tab[NS][65][NC];
__device__ float  g_th [NS][64];
__device__ float  g_wv [NS][4];

// ---------------------------------------------------------------------------
// Precompute (R10 verbatim — measured-best gap 7.9 us): grid (65, 5) x 64.
// fp64 channel meta + bitonic sort (exact k-bucketing); w2 staged via
// LDG.128; table sums in fp32 with 4 independent split accumulators.
// ---------------------------------------------------------------------------
__global__ void __launch_bounds__(64)
precompute_tab(
    const float* __restrict__ lp, const float* __restrict__ hp,
    const float* __restrict__ w1, const float* __restrict__ w2,
    const float* __restrict__ g1, const float* __restrict__ b1,
    const float* __restrict__ m1, const float* __restrict__ v1,
    const float* __restrict__ g2, const float* __restrict__ b2,
    const float* __restrict__ m2, const float* __restrict__ v2)
{
    const int s = blockIdx.y;
    const int k = blockIdx.x;       // 0..64
    const int c = threadIdx.x;      // 0..63

    __shared__ float  sw2[64 * 65];   // padded stride 65: conflict-free columns
    __shared__ float  sAf[64], sBf[64];
    __shared__ float  sthv[64];
    __shared__ int    sidx[64];
    __shared__ int    srk [64];
    __shared__ signed char scls[64];  // 1: A>0, 2: A<0, 3: A==0 && B>0, 0: dead

    // stage w2 with vector loads: 16 LDG.128 per thread
    {
        const float4* w2v = reinterpret_cast<const float4*>(w2) + s * 1024;
        #pragma unroll
        for (int t = 0; t < 16; t++) {
            const int i   = c + t * 64;       // float4 index 0..1023
            const float4 v = w2v[i];
            const int row = i >> 4;           // 16 float4 per row
            const int col = (i & 15) * 4;
            float* dst = &sw2[row * 65 + col];
            dst[0] = v.x; dst[1] = v.y; dst[2] = v.z; dst[3] = v.w;
        }
    }

    // per-channel meta in fp64 (k-bucketing identical to prior rounds)
    {
        double sc1 = (double)g1[s*NC + c] / sqrt((double)v1[s*NC + c] + 1e-5);
        double sh1 = (double)b1[s*NC + c] - (double)m1[s*NC + c] * sc1;
        double A   = (double)w1[s*NC + c] * sc1;
        sAf[c]  = (float)A;
        sBf[c]  = (float)sh1;
        scls[c] = (A > 0.0) ? 1 : (A < 0.0) ? 2 : (sh1 > 0.0) ? 3 : 0;
        sthv[c] = (A != 0.0) ? (float)(-sh1 / A) : CUDART_INF_F;
        sidx[c] = c;
    }
    __syncthreads();

    // bitonic sort of 64 (key sthv, payload sidx)
    for (int ksz = 2; ksz <= 64; ksz <<= 1) {
        for (int j = ksz >> 1; j > 0; j >>= 1) {
            int ixj = c ^ j;
            if (ixj > c) {
                float a = sthv[c], bb = sthv[ixj];
                int   ia = sidx[c], ib = sidx[ixj];
                bool  up = ((c & ksz) == 0);
                if (up ? (a > bb) : (a < bb)) {
                    sthv[c] = bb; sthv[ixj] = a;
                    sidx[c] = ib; sidx[ixj] = ia;
                }
            }
            __syncthreads();
        }
    }

    srk[sidx[c]] = c;
    if (k == 0) {
        g_th[s][c] = sthv[c];
        if (c == 0) {
            g_wv[s][0] = lp[s*2]; g_wv[s][1] = lp[s*2+1];
            g_wv[s][2] = hp[s*2]; g_wv[s][3] = hp[s*2+1];
        }
    }
    __syncthreads();

    // entry (s, k, o = c): fp32 masked sums, 4 independent chains
    const int o = c;
    const double sc2 = (double)g2[s*NC + o] / sqrt((double)v2[s*NC + o] + 1e-5);
    const double sh2 = (double)b2[s*NC + o] - (double)m2[s*NC + o] * sc2;

    float s1a = 0.f, s2a = 0.f, s1b = 0.f, s2b = 0.f;
    float s1c = 0.f, s2c = 0.f, s1d = 0.f, s2d = 0.f;
    #pragma unroll
    for (int cc = 0; cc < 64; cc += 4) {
        #define ACC(CI, S1, S2)                                          \
        {   const int cl = scls[CI];                                     \
            const bool act = (cl == 1) ? (srk[CI] < k)                   \
                           : (cl == 2) ? (srk[CI] >= k)                  \
                                       : (cl == 3);                      \
            if (act) {                                                   \
                const float w = sw2[o*65 + (CI)];                        \
                S1 = fmaf(w, sBf[CI], S1);                               \
                S2 = fmaf(w, sAf[CI], S2);                               \
            }                                                            \
        }
        ACC(cc + 0, s1a, s2a)
        ACC(cc + 1, s1b, s2b)
        ACC(cc + 2, s1c, s2c)
        ACC(cc + 3, s1d, s2d)
        #undef ACC
    }
    const double s1 = (double)((s1a + s1b) + (s1c + s1d));
    const double s2 = (double)((s2a + s2b) + (s2c + s2d));
    g_tab[s][k][o] = make_float2((float)(sc2*s1 + sh2), (float)(sc2*s2));
}

// ---------------------------------------------------------------------------
// Main kernel (code identical to R8/R10; grid switched to (30,40), the
// config with the best single measurement, 152.7 us in R3): thread owns 4
// consecutive pixels; STG.128 everywhere via per-plane shift d = o & 3 with
// a 7-slot (3 halo + 4 own) shfl window.
// ---------------------------------------------------------------------------
__global__ void __launch_bounds__(256)
dwt_pwl_kernel(const float* __restrict__ x, float* __restrict__ out)
{
    __shared__ float2 stab[65 * 65];   // idx = k*65 + o  (padded stride)
    __shared__ float  sth[64];

    const int sb = blockIdx.y;          // 0..39
    const int s  = sb / NB;
    const int b  = sb - s * NB;

    const float2* gt = &g_tab[s][0][0];
    for (int i = threadIdx.x; i < 65 * 64; i += 256) {
        int k = i >> 6, o = i & 63;
        stab[k * 65 + o] = gt[i];
    }
    if (threadIdx.x < 64) sth[threadIdx.x] = g_th[s][threadIdx.x];
    __syncthreads();

    const float lp0 = g_wv[s][0], lp1 = g_wv[s][1];
    const float hp0 = g_wv[s][2], hp1 = g_wv[s][3];

    const float* __restrict__ xb = x + (size_t)b * HIN * WIN;
    float* __restrict__ outL = out + (size_t)sb * NPIX;
    float* __restrict__ outH = out + (size_t)(NS*NB + sb) * NPIX;
    float* __restrict__ outP = out + (size_t)2*NS*NB*NPIX + (size_t)sb * NC * NPIX;

    const int lane = threadIdx.x & 31;
    const int gstride = gridDim.x * blockDim.x;

    // compute L, Hc, rank k for one pixel (fully guarded, incl. bottom row)
    auto pixLHK = [&](int pix, float& L, float& H, int& k) {
        L = 0.f; H = 0.f;
        if (pix >= 0 && pix < NPIX) {
            unsigned up = (unsigned)pix;
            int i = up / WO;
            int j = up - i * WO;
            int r0 = 2*i - 1, r1 = 2*i;
            int c0 = 2*j - 1, c1 = 2*j;
            float x00 = (r0 >= 0  && c0 >= 0 ) ? xb[r0*WIN + c0] : 0.f;
            float x01 = (r0 >= 0  && c1 < WIN) ? xb[r0*WIN + c1] : 0.f;
            float x10 = (r1 < HIN && c0 >= 0 ) ? xb[r1*WIN + c0] : 0.f;
            float x11 = (r1 < HIN && c1 < WIN) ? xb[r1*WIN + c1] : 0.f;
            L = lp0*(lp0*x00 + lp1*x01) + lp1*(lp0*x10 + lp1*x11);
            H = hp0*(hp0*x00 + hp1*x01) + hp1*(hp0*x10 + hp1*x11);
        }
        int kk = (sth[31]       < L) ? 32 : 0;
        kk += (sth[kk + 15] < L) ? 16 : 0;
        kk += (sth[kk +  7] < L) ?  8 : 0;
        kk += (sth[kk +  3] < L) ?  4 : 0;
        kk += (sth[kk +  1] < L) ?  2 : 0;
        kk += (sth[kk     ] < L) ?  1 : 0;
        k = kk;
    };

    for (int gw = blockIdx.x * 256 + (int)(threadIdx.x & ~31u); gw < NGRP;
         gw += gstride)
    {
        const int g = gw + lane;
        const int pix0 = 4 * g;

        float Ls[7], Hs[7]; int ks[7];
        pixLHK(pix0 + 0, Ls[3], Hs[3], ks[3]);
        pixLHK(pix0 + 1, Ls[4], Hs[4], ks[4]);
        pixLHK(pix0 + 2, Ls[5], Hs[5], ks[5]);
        pixLHK(pix0 + 3, Ls[6], Hs[6], ks[6]);

        // halo (previous group's pixels 1..3) via shfl; lane 0 recomputes
        Ls[0] = __shfl_up_sync(0xffffffffu, Ls[4], 1);
        Ls[1] = __shfl_up_sync(0xffffffffu, Ls[5], 1);
        Ls[2] = __shfl_up_sync(0xffffffffu, Ls[6], 1);
        Hs[0] = __shfl_up_sync(0xffffffffu, Hs[4], 1);
        Hs[1] = __shfl_up_sync(0xffffffffu, Hs[5], 1);
        Hs[2] = __shfl_up_sync(0xffffffffu, Hs[6], 1);
        ks[0] = __shfl_up_sync(0xffffffffu, ks[4], 1);
        ks[1] = __shfl_up_sync(0xffffffffu, ks[5], 1);
        ks[2] = __shfl_up_sync(0xffffffffu, ks[6], 1);
        if (lane == 0) {
            pixLHK(pix0 - 3, Ls[0], Hs[0], ks[0]);
            pixLHK(pix0 - 2, Ls[1], Hs[1], ks[1]);
            pixLHK(pix0 - 1, Ls[2], Hs[2], ks[2]);
        }

        if (g >= NGRP) continue;

        const bool edge = (g == 0) || (g == NGRP - 1);

        if (!edge) {
            // ---- P planes: 16 quads of 4 channels, one STG.128 each ----
            float* bp = outP + pix0;
            #pragma unroll
            for (int q = 0; q < 16; q++) {
                const int o0 = 4 * q;
                {   // o0, d=0: slots 3..6, addr +0
                    float2 f0 = stab[ks[3]*65 + o0], f1 = stab[ks[4]*65 + o0];
                    float2 f2 = stab[ks[5]*65 + o0], f3 = stab[ks[6]*65 + o0];
                    float4 v = make_float4(fmaxf(fmaf(f0.y, Ls[3], f0.x), 0.f),
                                           fmaxf(fmaf(f1.y, Ls[4], f1.x), 0.f),
                                           fmaxf(fmaf(f2.y, Ls[5], f2.x), 0.f),
                                           fmaxf(fmaf(f3.y, Ls[6], f3.x), 0.f));
                    *reinterpret_cast<float4*>(bp) = v;
                }
                {   // o0+1, d=1: slots 2..5, addr +NPIX-1
                    float2 f0 = stab[ks[2]*65 + o0+1], f1 = stab[ks[3]*65 + o0+1];
                    float2 f2 = stab[ks[4]*65 + o0+1], f3 = stab[ks[5]*65 + o0+1];
                    float4 v = make_float4(fmaxf(fmaf(f0.y, Ls[2], f0.x), 0.f),
                                           fmaxf(fmaf(f1.y, Ls[3], f1.x), 0.f),
                                           fmaxf(fmaf(f2.y, Ls[4], f2.x), 0.f),
                                           fmaxf(fmaf(f3.y, Ls[5], f3.x), 0.f));
                    *reinterpret_cast<float4*>(bp + (NPIX - 1)) = v;
                }
                {   // o0+2, d=2: slots 1..4, addr +2*NPIX-2
                    float2 f0 = stab[ks[1]*65 + o0+2], f1 = stab[ks[2]*65 + o0+2];
                    float2 f2 = stab[ks[3]*65 + o0+2], f3 = stab[ks[4]*65 + o0+2];
                    float4 v = make_float4(fmaxf(fmaf(f0.y, Ls[1], f0.x), 0.f),
                                           fmaxf(fmaf(f1.y, Ls[2], f1.x), 0.f),
                                           fmaxf(fmaf(f2.y, Ls[3], f2.x), 0.f),
                                           fmaxf(fmaf(f3.y, Ls[4], f3.x), 0.f));
                    *reinterpret_cast<float4*>(bp + (2*NPIX - 2)) = v;
                }
                {   // o0+3, d=3: slots 0..3, addr +3*NPIX-3
                    float2 f0 = stab[ks[0]*65 + o0+3], f1 = stab[ks[1]*65 + o0+3];
                    float2 f2 = stab[ks[2]*65 + o0+3], f3 = stab[ks[3]*65 + o0+3];
                    float4 v = make_float4(fmaxf(fmaf(f0.y, Ls[0], f0.x), 0.f),
                                           fmaxf(fmaf(f1.y, Ls[1], f1.x), 0.f),
                                           fmaxf(fmaf(f2.y, Ls[2], f2.x), 0.f),
                                           fmaxf(fmaf(f3.y, Ls[3], f3.x), 0.f));
                    *reinterpret_cast<float4*>(bp + (3*NPIX - 3)) = v;
                }
                bp += (size_t)4 * NPIX;
            }

            // ---- L / Hc planes: runtime shift (uniform per block) ----
            switch (sb & 3) {
            case 0:
                *reinterpret_cast<float4*>(outL + pix0) =
                    make_float4(Ls[3], Ls[4], Ls[5], Ls[6]);
                *reinterpret_cast<float4*>(outH + pix0) =
                    make_float4(Hs[3], Hs[4], Hs[5], Hs[6]);
                break;
            case 1:
                *reinterpret_cast<float4*>(outL + pix0 - 1) =
                    make_float4(Ls[2], Ls[3], Ls[4], Ls[5]);
                *reinterpret_cast<float4*>(outH + pix0 - 1) =
                    make_float4(Hs[2], Hs[3], Hs[4], Hs[5]);
                break;
            case 2:
                *reinterpret_cast<float4*>(outL + pix0 - 2) =
                    make_float4(Ls[1], Ls[2], Ls[3], Ls[4]);
                *reinterpret_cast<float4*>(outH + pix0 - 2) =
                    make_float4(Hs[1], Hs[2], Hs[3], Hs[4]);
                break;
            default:
                *reinterpret_cast<float4*>(outL + pix0 - 3) =
                    make_float4(Ls[0], Ls[1], Ls[2], Ls[3]);
                *reinterpret_cast<float4*>(outH + pix0 - 3) =
                    make_float4(Hs[0], Hs[1], Hs[2], Hs[3]);
                break;
            }
        } else {
            // ---- edge groups (first/last of plane): masked scalar stores ----
            #pragma unroll 4
            for (int o = 0; o < 64; o++) {
                const int d = o & 3;
                #pragma unroll
                for (int e = 0; e < 4; e++) {
                    int pix = pix0 - d + e;
                    if (pix >= 0 && pix < NPIX) {
                        float2 f = stab[ks[3 - d + e] * 65 + o];
                        outP[(size_t)o * NPIX + pix] =
                            fmaxf(fmaf(f.y, Ls[3 - d + e], f.x), 0.f);
                    }
                }
            }
            switch (sb & 3) {
            #define EDGE_LH(D)                                              \
                { _Pragma("unroll")                                         \
                  for (int e = 0; e < 4; e++) {                             \
                      int pix = pix0 - (D) + e;                             \
                      if (pix >= 0 && pix < NPIX) {                         \
                          outL[pix] = Ls[3 - (D) + e];                      \
                          outH[pix] = Hs[3 - (D) + e];                      \
                      }                                                     \
                  } }
            case 0:  EDGE_LH(0) break;
            case 1:  EDGE_LH(1) break;
            case 2:  EDGE_LH(2) break;
            default: EDGE_LH(3) break;
            #undef EDGE_LH
            }
        }
    }
}

// ---------------------------------------------------------------------------
extern "C" void kernel_launch(void* const* d_in, const int* in_sizes, int n_in,
                              void* d_out, int out_size)
{
    const float* x  = (const float*)d_in[0];
    const float* lp = (const float*)d_in[1];
    const float* hp = (const float*)d_in[2];
    const float* w1 = (const float*)d_in[3];
    const float* w2 = (const float*)d_in[4];
    const float* g1 = (const float*)d_in[5];
    const float* b1 = (const float*)d_in[6];
    const float* m1 = (const float*)d_in[7];
    const float* v1 = (const float*)d_in[8];
    const float* g2 = (const float*)d_in[9];
    const float* b2 = (const float*)d_in[10];
    const float* m2 = (const float*)d_in[11];
    const float* v2 = (const float*)d_in[12];
    float* out = (float*)d_out;

    precompute_tab<<<dim3(65, NS), 64>>>(lp, hp, w1, w2, g1, b1, m1, v1,
                                         g2, b2, m2, v2);

    dim3 grid(30, NS * NB);   // 1200 blocks — best single main measurement
    dwt_pwl_kernel<<<grid, 256>>>(x, out);
}

// round 12
// speedup vs baseline: 1.1836x; 1.0002x over previous
#include <cuda_runtime.h>
#include <math_constants.h>

#define NS   5
#define NC   64
#define NB   8
#define HIN  512
#define WIN  512
#define HO   257
#define WO   257
#define NPIX (HO*WO)            // 66049
#define NGRP ((NPIX + 3) / 4)   // 16513 groups of 4 pixels

// Piecewise-linear table, k-major, float2 {S1,S2}:
//   P[o](L) = max(S1 + S2*L, 0), k = #{sorted thresholds < L}
__device__ float2 g_tab[NS][65][NC];
__device__ float  g_th [NS][64];
__device__ float  g_wv [NS][4];

// ---------------------------------------------------------------------------
// Precompute (R10/R11 verbatim — measured-best): grid (65, 5) x 64.
// fp64 channel meta + bitonic sort (exact k-bucketing); w2 staged via
// LDG.128; table sums in fp32 with 4 independent split accumulators.
// ---------------------------------------------------------------------------
__global__ void __launch_bounds__(64)
precompute_tab(
    const float* __restrict__ lp, const float* __restrict__ hp,
    const float* __restrict__ w1, const float* __restrict__ w2,
    const float* __restrict__ g1, const float* __restrict__ b1,
    const float* __restrict__ m1, const float* __restrict__ v1,
    const float* __restrict__ g2, const float* __restrict__ b2,
    const float* __restrict__ m2, const float* __restrict__ v2)
{
    const int s = blockIdx.y;
    const int k = blockIdx.x;       // 0..64
    const int c = threadIdx.x;      // 0..63

    __shared__ float  sw2[64 * 65];   // padded stride 65: conflict-free columns
    __shared__ float  sAf[64], sBf[64];
    __shared__ float  sthv[64];
    __shared__ int    sidx[64];
    __shared__ int    srk [64];
    __shared__ signed char scls[64];  // 1: A>0, 2: A<0, 3: A==0 && B>0, 0: dead

    // stage w2 with vector loads: 16 LDG.128 per thread
    {
        const float4* w2v = reinterpret_cast<const float4*>(w2) + s * 1024;
        #pragma unroll
        for (int t = 0; t < 16; t++) {
            const int i   = c + t * 64;       // float4 index 0..1023
            const float4 v = w2v[i];
            const int row = i >> 4;           // 16 float4 per row
            const int col = (i & 15) * 4;
            float* dst = &sw2[row * 65 + col];
            dst[0] = v.x; dst[1] = v.y; dst[2] = v.z; dst[3] = v.w;
        }
    }

    // per-channel meta in fp64 (k-bucketing identical to prior rounds)
    {
        double sc1 = (double)g1[s*NC + c] / sqrt((double)v1[s*NC + c] + 1e-5);
        double sh1 = (double)b1[s*NC + c] - (double)m1[s*NC + c] * sc1;
        double A   = (double)w1[s*NC + c] * sc1;
        sAf[c]  = (float)A;
        sBf[c]  = (float)sh1;
        scls[c] = (A > 0.0) ? 1 : (A < 0.0) ? 2 : (sh1 > 0.0) ? 3 : 0;
        sthv[c] = (A != 0.0) ? (float)(-sh1 / A) : CUDART_INF_F;
        sidx[c] = c;
    }
    __syncthreads();

    // bitonic sort of 64 (key sthv, payload sidx)
    for (int ksz = 2; ksz <= 64; ksz <<= 1) {
        for (int j = ksz >> 1; j > 0; j >>= 1) {
            int ixj = c ^ j;
            if (ixj > c) {
                float a = sthv[c], bb = sthv[ixj];
                int   ia = sidx[c], ib = sidx[ixj];
                bool  up = ((c & ksz) == 0);
                if (up ? (a > bb) : (a < bb)) {
                    sthv[c] = bb; sthv[ixj] = a;
                    sidx[c] = ib; sidx[ixj] = ia;
                }
            }
            __syncthreads();
        }
    }

    srk[sidx[c]] = c;
    if (k == 0) {
        g_th[s][c] = sthv[c];
        if (c == 0) {
            g_wv[s][0] = lp[s*2]; g_wv[s][1] = lp[s*2+1];
            g_wv[s][2] = hp[s*2]; g_wv[s][3] = hp[s*2+1];
        }
    }
    __syncthreads();

    // entry (s, k, o = c): fp32 masked sums, 4 independent chains
    const int o = c;
    const double sc2 = (double)g2[s*NC + o] / sqrt((double)v2[s*NC + o] + 1e-5);
    const double sh2 = (double)b2[s*NC + o] - (double)m2[s*NC + o] * sc2;

    float s1a = 0.f, s2a = 0.f, s1b = 0.f, s2b = 0.f;
    float s1c = 0.f, s2c = 0.f, s1d = 0.f, s2d = 0.f;
    #pragma unroll
    for (int cc = 0; cc < 64; cc += 4) {
        #define ACC(CI, S1, S2)                                          \
        {   const int cl = scls[CI];                                     \
            const bool act = (cl == 1) ? (srk[CI] < k)                   \
                           : (cl == 2) ? (srk[CI] >= k)                  \
                                       : (cl == 3);                      \
            if (act) {                                                   \
                const float w = sw2[o*65 + (CI)];                        \
                S1 = fmaf(w, sBf[CI], S1);                               \
                S2 = fmaf(w, sAf[CI], S2);                               \
            }                                                            \
        }
        ACC(cc + 0, s1a, s2a)
        ACC(cc + 1, s1b, s2b)
        ACC(cc + 2, s1c, s2c)
        ACC(cc + 3, s1d, s2d)
        #undef ACC
    }
    const double s1 = (double)((s1a + s1b) + (s1c + s1d));
    const double s2 = (double)((s2a + s2b) + (s2c + s2d));
    g_tab[s][k][o] = make_float2((float)(sc2*s1 + sh2), (float)(sc2*s2));
}

// ---------------------------------------------------------------------------
// Main kernel (code identical to R11; grid.x 30 -> 45 for finer tail
// balancing): thread owns 4 consecutive pixels; STG.128 everywhere via
// per-plane shift d = o & 3 with a 7-slot (3 halo + 4 own) shfl window.
// ---------------------------------------------------------------------------
__global__ void __launch_bounds__(256)
dwt_pwl_kernel(const float* __restrict__ x, float* __restrict__ out)
{
    __shared__ float2 stab[65 * 65];   // idx = k*65 + o  (padded stride)
    __shared__ float  sth[64];

    const int sb = blockIdx.y;          // 0..39
    const int s  = sb / NB;
    const int b  = sb - s * NB;

    const float2* gt = &g_tab[s][0][0];
    for (int i = threadIdx.x; i < 65 * 64; i += 256) {
        int k = i >> 6, o = i & 63;
        stab[k * 65 + o] = gt[i];
    }
    if (threadIdx.x < 64) sth[threadIdx.x] = g_th[s][threadIdx.x];
    __syncthreads();

    const float lp0 = g_wv[s][0], lp1 = g_wv[s][1];
    const float hp0 = g_wv[s][2], hp1 = g_wv[s][3];

    const float* __restrict__ xb = x + (size_t)b * HIN * WIN;
    float* __restrict__ outL = out + (size_t)sb * NPIX;
    float* __restrict__ outH = out + (size_t)(NS*NB + sb) * NPIX;
    float* __restrict__ outP = out + (size_t)2*NS*NB*NPIX + (size_t)sb * NC * NPIX;

    const int lane = threadIdx.x & 31;
    const int gstride = gridDim.x * blockDim.x;

    // compute L, Hc, rank k for one pixel (fully guarded, incl. bottom row)
    auto pixLHK = [&](int pix, float& L, float& H, int& k) {
        L = 0.f; H = 0.f;
        if (pix >= 0 && pix < NPIX) {
            unsigned up = (unsigned)pix;
            int i = up / WO;
            int j = up - i * WO;
            int r0 = 2*i - 1, r1 = 2*i;
            int c0 = 2*j - 1, c1 = 2*j;
            float x00 = (r0 >= 0  && c0 >= 0 ) ? xb[r0*WIN + c0] : 0.f;
            float x01 = (r0 >= 0  && c1 < WIN) ? xb[r0*WIN + c1] : 0.f;
            float x10 = (r1 < HIN && c0 >= 0 ) ? xb[r1*WIN + c0] : 0.f;
            float x11 = (r1 < HIN && c1 < WIN) ? xb[r1*WIN + c1] : 0.f;
            L = lp0*(lp0*x00 + lp1*x01) + lp1*(lp0*x10 + lp1*x11);
            H = hp0*(hp0*x00 + hp1*x01) + hp1*(hp0*x10 + hp1*x11);
        }
        int kk = (sth[31]       < L) ? 32 : 0;
        kk += (sth[kk + 15] < L) ? 16 : 0;
        kk += (sth[kk +  7] < L) ?  8 : 0;
        kk += (sth[kk +  3] < L) ?  4 : 0;
        kk += (sth[kk +  1] < L) ?  2 : 0;
        kk += (sth[kk     ] < L) ?  1 : 0;
        k = kk;
    };

    for (int gw = blockIdx.x * 256 + (int)(threadIdx.x & ~31u); gw < NGRP;
         gw += gstride)
    {
        const int g = gw + lane;
        const int pix0 = 4 * g;

        float Ls[7], Hs[7]; int ks[7];
        pixLHK(pix0 + 0, Ls[3], Hs[3], ks[3]);
        pixLHK(pix0 + 1, Ls[4], Hs[4], ks[4]);
        pixLHK(pix0 + 2, Ls[5], Hs[5], ks[5]);
        pixLHK(pix0 + 3, Ls[6], Hs[6], ks[6]);

        // halo (previous group's pixels 1..3) via shfl; lane 0 recomputes
        Ls[0] = __shfl_up_sync(0xffffffffu, Ls[4], 1);
        Ls[1] = __shfl_up_sync(0xffffffffu, Ls[5], 1);
        Ls[2] = __shfl_up_sync(0xffffffffu, Ls[6], 1);
        Hs[0] = __shfl_up_sync(0xffffffffu, Hs[4], 1);
        Hs[1] = __shfl_up_sync(0xffffffffu, Hs[5], 1);
        Hs[2] = __shfl_up_sync(0xffffffffu, Hs[6], 1);
        ks[0] = __shfl_up_sync(0xffffffffu, ks[4], 1);
        ks[1] = __shfl_up_sync(0xffffffffu, ks[5], 1);
        ks[2] = __shfl_up_sync(0xffffffffu, ks[6], 1);
        if (lane == 0) {
            pixLHK(pix0 - 3, Ls[0], Hs[0], ks[0]);
            pixLHK(pix0 - 2, Ls[1], Hs[1], ks[1]);
            pixLHK(pix0 - 1, Ls[2], Hs[2], ks[2]);
        }

        if (g >= NGRP) continue;

        const bool edge = (g == 0) || (g == NGRP - 1);

        if (!edge) {
            // ---- P planes: 16 quads of 4 channels, one STG.128 each ----
            float* bp = outP + pix0;
            #pragma unroll
            for (int q = 0; q < 16; q++) {
                const int o0 = 4 * q;
                {   // o0, d=0: slots 3..6, addr +0
                    float2 f0 = stab[ks[3]*65 + o0], f1 = stab[ks[4]*65 + o0];
                    float2 f2 = stab[ks[5]*65 + o0], f3 = stab[ks[6]*65 + o0];
                    float4 v = make_float4(fmaxf(fmaf(f0.y, Ls[3], f0.x), 0.f),
                                           fmaxf(fmaf(f1.y, Ls[4], f1.x), 0.f),
                                           fmaxf(fmaf(f2.y, Ls[5], f2.x), 0.f),
                                           fmaxf(fmaf(f3.y, Ls[6], f3.x), 0.f));
                    *reinterpret_cast<float4*>(bp) = v;
                }
                {   // o0+1, d=1: slots 2..5, addr +NPIX-1
                    float2 f0 = stab[ks[2]*65 + o0+1], f1 = stab[ks[3]*65 + o0+1];
                    float2 f2 = stab[ks[4]*65 + o0+1], f3 = stab[ks[5]*65 + o0+1];
                    float4 v = make_float4(fmaxf(fmaf(f0.y, Ls[2], f0.x), 0.f),
                                           fmaxf(fmaf(f1.y, Ls[3], f1.x), 0.f),
                                           fmaxf(fmaf(f2.y, Ls[4], f2.x), 0.f),
                                           fmaxf(fmaf(f3.y, Ls[5], f3.x), 0.f));
                    *reinterpret_cast<float4*>(bp + (NPIX - 1)) = v;
                }
                {   // o0+2, d=2: slots 1..4, addr +2*NPIX-2
                    float2 f0 = stab[ks[1]*65 + o0+2], f1 = stab[ks[2]*65 + o0+2];
                    float2 f2 = stab[ks[3]*65 + o0+2], f3 = stab[ks[4]*65 + o0+2];
                    float4 v = make_float4(fmaxf(fmaf(f0.y, Ls[1], f0.x), 0.f),
                                           fmaxf(fmaf(f1.y, Ls[2], f1.x), 0.f),
                                           fmaxf(fmaf(f2.y, Ls[3], f2.x), 0.f),
                                           fmaxf(fmaf(f3.y, Ls[4], f3.x), 0.f));
                    *reinterpret_cast<float4*>(bp + (2*NPIX - 2)) = v;
                }
                {   // o0+3, d=3: slots 0..3, addr +3*NPIX-3
                    float2 f0 = stab[ks[0]*65 + o0+3], f1 = stab[ks[1]*65 + o0+3];
                    float2 f2 = stab[ks[2]*65 + o0+3], f3 = stab[ks[3]*65 + o0+3];
                    float4 v = make_float4(fmaxf(fmaf(f0.y, Ls[0], f0.x), 0.f),
                                           fmaxf(fmaf(f1.y, Ls[1], f1.x), 0.f),
                                           fmaxf(fmaf(f2.y, Ls[2], f2.x), 0.f),
                                           fmaxf(fmaf(f3.y, Ls[3], f3.x), 0.f));
                    *reinterpret_cast<float4*>(bp + (3*NPIX - 3)) = v;
                }
                bp += (size_t)4 * NPIX;
            }

            // ---- L / Hc planes: runtime shift (uniform per block) ----
            switch (sb & 3) {
            case 0:
                *reinterpret_cast<float4*>(outL + pix0) =
                    make_float4(Ls[3], Ls[4], Ls[5], Ls[6]);
                *reinterpret_cast<float4*>(outH + pix0) =
                    make_float4(Hs[3], Hs[4], Hs[5], Hs[6]);
                break;
            case 1:
                *reinterpret_cast<float4*>(outL + pix0 - 1) =
                    make_float4(Ls[2], Ls[3], Ls[4], Ls[5]);
                *reinterpret_cast<float4*>(outH + pix0 - 1) =
                    make_float4(Hs[2], Hs[3], Hs[4], Hs[5]);
                break;
            case 2:
                *reinterpret_cast<float4*>(outL + pix0 - 2) =
                    make_float4(Ls[1], Ls[2], Ls[3], Ls[4]);
                *reinterpret_cast<float4*>(outH + pix0 - 2) =
                    make_float4(Hs[1], Hs[2], Hs[3], Hs[4]);
                break;
            default:
                *reinterpret_cast<float4*>(outL + pix0 - 3) =
                    make_float4(Ls[0], Ls[1], Ls[2], Ls[3]);
                *reinterpret_cast<float4*>(outH + pix0 - 3) =
                    make_float4(Hs[0], Hs[1], Hs[2], Hs[3]);
                break;
            }
        } else {
            // ---- edge groups (first/last of plane): masked scalar stores ----
            #pragma unroll 4
            for (int o = 0; o < 64; o++) {
                const int d = o & 3;
                #pragma unroll
                for (int e = 0; e < 4; e++) {
                    int pix = pix0 - d + e;
                    if (pix >= 0 && pix < NPIX) {
                        float2 f = stab[ks[3 - d + e] * 65 + o];
                        outP[(size_t)o * NPIX + pix] =
                            fmaxf(fmaf(f.y, Ls[3 - d + e], f.x), 0.f);
                    }
                }
            }
            switch (sb & 3) {
            #define EDGE_LH(D)                                              \
                { _Pragma("unroll")                                         \
                  for (int e = 0; e < 4; e++) {                             \
                      int pix = pix0 - (D) + e;                             \
                      if (pix >= 0 && pix < NPIX) {                         \
                          outL[pix] = Ls[3 - (D) + e];                      \
                          outH[pix] = Hs[3 - (D) + e];                      \
                      }                                                     \
                  } }
            case 0:  EDGE_LH(0) break;
            case 1:  EDGE_LH(1) break;
            case 2:  EDGE_LH(2) break;
            default: EDGE_LH(3) break;
            #undef EDGE_LH
            }
        }
    }
}

// ---------------------------------------------------------------------------
extern "C" void kernel_launch(void* const* d_in, const int* in_sizes, int n_in,
                              void* d_out, int out_size)
{
    const float* x  = (const float*)d_in[0];
    const float* lp = (const float*)d_in[1];
    const float* hp = (const float*)d_in[2];
    const float* w1 = (const float*)d_in[3];
    const float* w2 = (const float*)d_in[4];
    const float* g1 = (const float*)d_in[5];
    const float* b1 = (const float*)d_in[6];
    const float* m1 = (const float*)d_in[7];
    const float* v1 = (const float*)d_in[8];
    const float* g2 = (const float*)d_in[9];
    const float* b2 = (const float*)d_in[10];
    const float* m2 = (const float*)d_in[11];
    const float* v2 = (const float*)d_in[12];
    float* out = (float*)d_out;

    precompute_tab<<<dim3(65, NS), 64>>>(lp, hp, w1, w2, g1, b1, m1, v1,
                                         g2, b2, m2, v2);

    dim3 grid(45, NS * NB);   // 1800 blocks: finer tail balancing vs 1200
    dwt_pwl_kernel<<<grid, 256>>>(x, out);
}

// round 13
// speedup vs baseline: 1.2182x; 1.0292x over previous
#include <cuda_runtime.h>
#include <math_constants.h>

#define NS   5
#define NC   64
#define NB   8
#define HIN  512
#define WIN  512
#define HO   257
#define WO   257
#define NPIX (HO*WO)            // 66049
#define NGRP ((NPIX + 3) / 4)   // 16513 groups of 4 pixels

// Piecewise-linear table, k-major, float2 {S1,S2}:
//   P[o](L) = max(S1 + S2*L, 0), k = #{sorted thresholds < L}
__device__ float2 g_tab[NS][65][NC];
__device__ float  g_th [NS][64];
__device__ float  g_wv [NS][4];

// ---------------------------------------------------------------------------
// Precompute (R10/R11 verbatim — measured-best): grid (65, 5) x 64.
// fp64 channel meta + bitonic sort (exact k-bucketing); w2 staged via
// LDG.128; table sums in fp32 with 4 independent split accumulators.
// ---------------------------------------------------------------------------
__global__ void __launch_bounds__(64)
precompute_tab(
    const float* __restrict__ lp, const float* __restrict__ hp,
    const float* __restrict__ w1, const float* __restrict__ w2,
    const float* __restrict__ g1, const float* __restrict__ b1,
    const float* __restrict__ m1, const float* __restrict__ v1,
    const float* __restrict__ g2, const float* __restrict__ b2,
    const float* __restrict__ m2, const float* __restrict__ v2)
{
    const int s = blockIdx.y;
    const int k = blockIdx.x;       // 0..64
    const int c = threadIdx.x;      // 0..63

    __shared__ float  sw2[64 * 65];   // padded stride 65: conflict-free columns
    __shared__ float  sAf[64], sBf[64];
    __shared__ float  sthv[64];
    __shared__ int    sidx[64];
    __shared__ int    srk [64];
    __shared__ signed char scls[64];  // 1: A>0, 2: A<0, 3: A==0 && B>0, 0: dead

    // stage w2 with vector loads: 16 LDG.128 per thread
    {
        const float4* w2v = reinterpret_cast<const float4*>(w2) + s * 1024;
        #pragma unroll
        for (int t = 0; t < 16; t++) {
            const int i   = c + t * 64;       // float4 index 0..1023
            const float4 v = w2v[i];
            const int row = i >> 4;           // 16 float4 per row
            const int col = (i & 15) * 4;
            float* dst = &sw2[row * 65 + col];
            dst[0] = v.x; dst[1] = v.y; dst[2] = v.z; dst[3] = v.w;
        }
    }

    // per-channel meta in fp64 (k-bucketing identical to prior rounds)
    {
        double sc1 = (double)g1[s*NC + c] / sqrt((double)v1[s*NC + c] + 1e-5);
        double sh1 = (double)b1[s*NC + c] - (double)m1[s*NC + c] * sc1;
        double A   = (double)w1[s*NC + c] * sc1;
        sAf[c]  = (float)A;
        sBf[c]  = (float)sh1;
        scls[c] = (A > 0.0) ? 1 : (A < 0.0) ? 2 : (sh1 > 0.0) ? 3 : 0;
        sthv[c] = (A != 0.0) ? (float)(-sh1 / A) : CUDART_INF_F;
        sidx[c] = c;
    }
    __syncthreads();

    // bitonic sort of 64 (key sthv, payload sidx)
    for (int ksz = 2; ksz <= 64; ksz <<= 1) {
        for (int j = ksz >> 1; j > 0; j >>= 1) {
            int ixj = c ^ j;
            if (ixj > c) {
                float a = sthv[c], bb = sthv[ixj];
                int   ia = sidx[c], ib = sidx[ixj];
                bool  up = ((c & ksz) == 0);
                if (up ? (a > bb) : (a < bb)) {
                    sthv[c] = bb; sthv[ixj] = a;
                    sidx[c] = ib; sidx[ixj] = ia;
                }
            }
            __syncthreads();
        }
    }

    srk[sidx[c]] = c;
    if (k == 0) {
        g_th[s][c] = sthv[c];
        if (c == 0) {
            g_wv[s][0] = lp[s*2]; g_wv[s][1] = lp[s*2+1];
            g_wv[s][2] = hp[s*2]; g_wv[s][3] = hp[s*2+1];
        }
    }
    __syncthreads();

    // entry (s, k, o = c): fp32 masked sums, 4 independent chains
    const int o = c;
    const double sc2 = (double)g2[s*NC + o] / sqrt((double)v2[s*NC + o] + 1e-5);
    const double sh2 = (double)b2[s*NC + o] - (double)m2[s*NC + o] * sc2;

    float s1a = 0.f, s2a = 0.f, s1b = 0.f, s2b = 0.f;
    float s1c = 0.f, s2c = 0.f, s1d = 0.f, s2d = 0.f;
    #pragma unroll
    for (int cc = 0; cc < 64; cc += 4) {
        #define ACC(CI, S1, S2)                                          \
        {   const int cl = scls[CI];                                     \
            const bool act = (cl == 1) ? (srk[CI] < k)                   \
                           : (cl == 2) ? (srk[CI] >= k)                  \
                                       : (cl == 3);                      \
            if (act) {                                                   \
                const float w = sw2[o*65 + (CI)];                        \
                S1 = fmaf(w, sBf[CI], S1);                               \
                S2 = fmaf(w, sAf[CI], S2);                               \
            }                                                            \
        }
        ACC(cc + 0, s1a, s2a)
        ACC(cc + 1, s1b, s2b)
        ACC(cc + 2, s1c, s2c)
        ACC(cc + 3, s1d, s2d)
        #undef ACC
    }
    const double s1 = (double)((s1a + s1b) + (s1c + s1d));
    const double s2 = (double)((s2a + s2b) + (s2c + s2d));
    g_tab[s][k][o] = make_float2((float)(sc2*s1 + sh2), (float)(sc2*s2));
}

// ---------------------------------------------------------------------------
// Main kernel (R11 config — best measured 147.5 us at grid (30,40)) with
// streaming-store hints (__stcs) on the write-once output: thread owns 4
// consecutive pixels; STG.128 everywhere via per-plane shift d = o & 3 with
// a 7-slot (3 halo + 4 own) shfl window.
// ---------------------------------------------------------------------------
__global__ void __launch_bounds__(256)
dwt_pwl_kernel(const float* __restrict__ x, float* __restrict__ out)
{
    __shared__ float2 stab[65 * 65];   // idx = k*65 + o  (padded stride)
    __shared__ float  sth[64];

    const int sb = blockIdx.y;          // 0..39
    const int s  = sb / NB;
    const int b  = sb - s * NB;

    const float2* gt = &g_tab[s][0][0];
    for (int i = threadIdx.x; i < 65 * 64; i += 256) {
        int k = i >> 6, o = i & 63;
        stab[k * 65 + o] = gt[i];
    }
    if (threadIdx.x < 64) sth[threadIdx.x] = g_th[s][threadIdx.x];
    __syncthreads();

    const float lp0 = g_wv[s][0], lp1 = g_wv[s][1];
    const float hp0 = g_wv[s][2], hp1 = g_wv[s][3];

    const float* __restrict__ xb = x + (size_t)b * HIN * WIN;
    float* __restrict__ outL = out + (size_t)sb * NPIX;
    float* __restrict__ outH = out + (size_t)(NS*NB + sb) * NPIX;
    float* __restrict__ outP = out + (size_t)2*NS*NB*NPIX + (size_t)sb * NC * NPIX;

    const int lane = threadIdx.x & 31;
    const int gstride = gridDim.x * blockDim.x;

    // compute L, Hc, rank k for one pixel (fully guarded, incl. bottom row)
    auto pixLHK = [&](int pix, float& L, float& H, int& k) {
        L = 0.f; H = 0.f;
        if (pix >= 0 && pix < NPIX) {
            unsigned up = (unsigned)pix;
            int i = up / WO;
            int j = up - i * WO;
            int r0 = 2*i - 1, r1 = 2*i;
            int c0 = 2*j - 1, c1 = 2*j;
            float x00 = (r0 >= 0  && c0 >= 0 ) ? xb[r0*WIN + c0] : 0.f;
            float x01 = (r0 >= 0  && c1 < WIN) ? xb[r0*WIN + c1] : 0.f;
            float x10 = (r1 < HIN && c0 >= 0 ) ? xb[r1*WIN + c0] : 0.f;
            float x11 = (r1 < HIN && c1 < WIN) ? xb[r1*WIN + c1] : 0.f;
            L = lp0*(lp0*x00 + lp1*x01) + lp1*(lp0*x10 + lp1*x11);
            H = hp0*(hp0*x00 + hp1*x01) + hp1*(hp0*x10 + hp1*x11);
        }
        int kk = (sth[31]       < L) ? 32 : 0;
        kk += (sth[kk + 15] < L) ? 16 : 0;
        kk += (sth[kk +  7] < L) ?  8 : 0;
        kk += (sth[kk +  3] < L) ?  4 : 0;
        kk += (sth[kk +  1] < L) ?  2 : 0;
        kk += (sth[kk     ] < L) ?  1 : 0;
        k = kk;
    };

    for (int gw = blockIdx.x * 256 + (int)(threadIdx.x & ~31u); gw < NGRP;
         gw += gstride)
    {
        const int g = gw + lane;
        const int pix0 = 4 * g;

        float Ls[7], Hs[7]; int ks[7];
        pixLHK(pix0 + 0, Ls[3], Hs[3], ks[3]);
        pixLHK(pix0 + 1, Ls[4], Hs[4], ks[4]);
        pixLHK(pix0 + 2, Ls[5], Hs[5], ks[5]);
        pixLHK(pix0 + 3, Ls[6], Hs[6], ks[6]);

        // halo (previous group's pixels 1..3) via shfl; lane 0 recomputes
        Ls[0] = __shfl_up_sync(0xffffffffu, Ls[4], 1);
        Ls[1] = __shfl_up_sync(0xffffffffu, Ls[5], 1);
        Ls[2] = __shfl_up_sync(0xffffffffu, Ls[6], 1);
        Hs[0] = __shfl_up_sync(0xffffffffu, Hs[4], 1);
        Hs[1] = __shfl_up_sync(0xffffffffu, Hs[5], 1);
        Hs[2] = __shfl_up_sync(0xffffffffu, Hs[6], 1);
        ks[0] = __shfl_up_sync(0xffffffffu, ks[4], 1);
        ks[1] = __shfl_up_sync(0xffffffffu, ks[5], 1);
        ks[2] = __shfl_up_sync(0xffffffffu, ks[6], 1);
        if (lane == 0) {
            pixLHK(pix0 - 3, Ls[0], Hs[0], ks[0]);
            pixLHK(pix0 - 2, Ls[1], Hs[1], ks[1]);
            pixLHK(pix0 - 1, Ls[2], Hs[2], ks[2]);
        }

        if (g >= NGRP) continue;

        const bool edge = (g == 0) || (g == NGRP - 1);

        if (!edge) {
            // ---- P planes: 16 quads of 4 channels, one streaming STG.128 ----
            float* bp = outP + pix0;
            #pragma unroll
            for (int q = 0; q < 16; q++) {
                const int o0 = 4 * q;
                {   // o0, d=0: slots 3..6, addr +0
                    float2 f0 = stab[ks[3]*65 + o0], f1 = stab[ks[4]*65 + o0];
                    float2 f2 = stab[ks[5]*65 + o0], f3 = stab[ks[6]*65 + o0];
                    float4 v = make_float4(fmaxf(fmaf(f0.y, Ls[3], f0.x), 0.f),
                                           fmaxf(fmaf(f1.y, Ls[4], f1.x), 0.f),
                                           fmaxf(fmaf(f2.y, Ls[5], f2.x), 0.f),
                                           fmaxf(fmaf(f3.y, Ls[6], f3.x), 0.f));
                    __stcs(reinterpret_cast<float4*>(bp), v);
                }
                {   // o0+1, d=1: slots 2..5, addr +NPIX-1
                    float2 f0 = stab[ks[2]*65 + o0+1], f1 = stab[ks[3]*65 + o0+1];
                    float2 f2 = stab[ks[4]*65 + o0+1], f3 = stab[ks[5]*65 + o0+1];
                    float4 v = make_float4(fmaxf(fmaf(f0.y, Ls[2], f0.x), 0.f),
                                           fmaxf(fmaf(f1.y, Ls[3], f1.x), 0.f),
                                           fmaxf(fmaf(f2.y, Ls[4], f2.x), 0.f),
                                           fmaxf(fmaf(f3.y, Ls[5], f3.x), 0.f));
                    __stcs(reinterpret_cast<float4*>(bp + (NPIX - 1)), v);
                }
                {   // o0+2, d=2: slots 1..4, addr +2*NPIX-2
                    float2 f0 = stab[ks[1]*65 + o0+2], f1 = stab[ks[2]*65 + o0+2];
                    float2 f2 = stab[ks[3]*65 + o0+2], f3 = stab[ks[4]*65 + o0+2];
                    float4 v = make_float4(fmaxf(fmaf(f0.y, Ls[1], f0.x), 0.f),
                                           fmaxf(fmaf(f1.y, Ls[2], f1.x), 0.f),
                                           fmaxf(fmaf(f2.y, Ls[3], f2.x), 0.f),
                                           fmaxf(fmaf(f3.y, Ls[4], f3.x), 0.f));
                    __stcs(reinterpret_cast<float4*>(bp + (2*NPIX - 2)), v);
                }
                {   // o0+3, d=3: slots 0..3, addr +3*NPIX-3
                    float2 f0 = stab[ks[0]*65 + o0+3], f1 = stab[ks[1]*65 + o0+3];
                    float2 f2 = stab[ks[2]*65 + o0+3], f3 = stab[ks[3]*65 + o0+3];
                    float4 v = make_float4(fmaxf(fmaf(f0.y, Ls[0], f0.x), 0.f),
                                           fmaxf(fmaf(f1.y, Ls[1], f1.x), 0.f),
                                           fmaxf(fmaf(f2.y, Ls[2], f2.x), 0.f),
                                           fmaxf(fmaf(f3.y, Ls[3], f3.x), 0.f));
                    __stcs(reinterpret_cast<float4*>(bp + (3*NPIX - 3)), v);
                }
                bp += (size_t)4 * NPIX;
            }

            // ---- L / Hc planes: runtime shift (uniform per block) ----
            switch (sb & 3) {
            case 0:
                __stcs(reinterpret_cast<float4*>(outL + pix0),
                       make_float4(Ls[3], Ls[4], Ls[5], Ls[6]));
                __stcs(reinterpret_cast<float4*>(outH + pix0),
                       make_float4(Hs[3], Hs[4], Hs[5], Hs[6]));
                break;
            case 1:
                __stcs(reinterpret_cast<float4*>(outL + pix0 - 1),
                       make_float4(Ls[2], Ls[3], Ls[4], Ls[5]));
                __stcs(reinterpret_cast<float4*>(outH + pix0 - 1),
                       make_float4(Hs[2], Hs[3], Hs[4], Hs[5]));
                break;
            case 2:
                __stcs(reinterpret_cast<float4*>(outL + pix0 - 2),
                       make_float4(Ls[1], Ls[2], Ls[3], Ls[4]));
                __stcs(reinterpret_cast<float4*>(outH + pix0 - 2),
                       make_float4(Hs[1], Hs[2], Hs[3], Hs[4]));
                break;
            default:
                __stcs(reinterpret_cast<float4*>(outL + pix0 - 3),
                       make_float4(Ls[0], Ls[1], Ls[2], Ls[3]));
                __stcs(reinterpret_cast<float4*>(outH + pix0 - 3),
                       make_float4(Hs[0], Hs[1], Hs[2], Hs[3]));
                break;
            }
        } else {
            // ---- edge groups (first/last of plane): masked scalar stores ----
            #pragma unroll 4
            for (int o = 0; o < 64; o++) {
                const int d = o & 3;
                #pragma unroll
                for (int e = 0; e < 4; e++) {
                    int pix = pix0 - d + e;
                    if (pix >= 0 && pix < NPIX) {
                        float2 f = stab[ks[3 - d + e] * 65 + o];
                        outP[(size_t)o * NPIX + pix] =
                            fmaxf(fmaf(f.y, Ls[3 - d + e], f.x), 0.f);
                    }
                }
            }
            switch (sb & 3) {
            #define EDGE_LH(D)                                              \
                { _Pragma("unroll")                                         \
                  for (int e = 0; e < 4; e++) {                             \
                      int pix = pix0 - (D) + e;                             \
                      if (pix >= 0 && pix < NPIX) {                         \
                          outL[pix] = Ls[3 - (D) + e];                      \
                          outH[pix] = Hs[3 - (D) + e];                      \
                      }                                                     \
                  } }
            case 0:  EDGE_LH(0) break;
            case 1:  EDGE_LH(1) break;
            case 2:  EDGE_LH(2) break;
            default: EDGE_LH(3) break;
            #undef EDGE_LH
            }
        }
    }
}

// ---------------------------------------------------------------------------
extern "C" void kernel_launch(void* const* d_in, const int* in_sizes, int n_in,
                              void* d_out, int out_size)
{
    const float* x  = (const float*)d_in[0];
    const float* lp = (const float*)d_in[1];
    const float* hp = (const float*)d_in[2];
    const float* w1 = (const float*)d_in[3];
    const float* w2 = (const float*)d_in[4];
    const float* g1 = (const float*)d_in[5];
    const float* b1 = (const float*)d_in[6];
    const float* m1 = (const float*)d_in[7];
    const float* v1 = (const float*)d_in[8];
    const float* g2 = (const float*)d_in[9];
    const float* b2 = (const float*)d_in[10];
    const float* m2 = (const float*)d_in[11];
    const float* v2 = (const float*)d_in[12];
    float* out = (float*)d_out;

    precompute_tab<<<dim3(65, NS), 64>>>(lp, hp, w1, w2, g1, b1, m1, v1,
                                         g2, b2, m2, v2);

    dim3 grid(30, NS * NB);   // 1200 blocks — best-measured main config
    dwt_pwl_kernel<<<grid, 256>>>(x, out);
}

// round 14
// speedup vs baseline: 1.2212x; 1.0024x over previous
#include <cuda_runtime.h>
#include <math_constants.h>

#define NS   5
#define NC   64
#define NB   8
#define HIN  512
#define WIN  512
#define HO   257
#define WO   257
#define NPIX (HO*WO)            // 66049
#define NGRP ((NPIX + 3) / 4)   // 16513 groups of 4 pixels

// Piecewise-linear table, k-major, float2 {S1,S2}:
//   P[o](L) = max(S1 + S2*L, 0), k = #{sorted thresholds < L}
__device__ float2 g_tab[NS][65][NC];
__device__ float  g_th [NS][64];
__device__ float  g_wv [NS][4];

// ---------------------------------------------------------------------------
// Precompute (R10-R13 verbatim — measured-best): grid (65, 5) x 64.
// fp64 channel meta + bitonic sort (exact k-bucketing); w2 staged via
// LDG.128; table sums in fp32 with 4 independent split accumulators.
// ---------------------------------------------------------------------------
__global__ void __launch_bounds__(64)
precompute_tab(
    const float* __restrict__ lp, const float* __restrict__ hp,
    const float* __restrict__ w1, const float* __restrict__ w2,
    const float* __restrict__ g1, const float* __restrict__ b1,
    const float* __restrict__ m1, const float* __restrict__ v1,
    const float* __restrict__ g2, const float* __restrict__ b2,
    const float* __restrict__ m2, const float* __restrict__ v2)
{
    const int s = blockIdx.y;
    const int k = blockIdx.x;       // 0..64
    const int c = threadIdx.x;      // 0..63

    __shared__ float  sw2[64 * 65];   // padded stride 65: conflict-free columns
    __shared__ float  sAf[64], sBf[64];
    __shared__ float  sthv[64];
    __shared__ int    sidx[64];
    __shared__ int    srk [64];
    __shared__ signed char scls[64];  // 1: A>0, 2: A<0, 3: A==0 && B>0, 0: dead

    // stage w2 with vector loads: 16 LDG.128 per thread
    {
        const float4* w2v = reinterpret_cast<const float4*>(w2) + s * 1024;
        #pragma unroll
        for (int t = 0; t < 16; t++) {
            const int i   = c + t * 64;       // float4 index 0..1023
            const float4 v = w2v[i];
            const int row = i >> 4;           // 16 float4 per row
            const int col = (i & 15) * 4;
            float* dst = &sw2[row * 65 + col];
            dst[0] = v.x; dst[1] = v.y; dst[2] = v.z; dst[3] = v.w;
        }
    }

    // per-channel meta in fp64 (k-bucketing identical to prior rounds)
    {
        double sc1 = (double)g1[s*NC + c] / sqrt((double)v1[s*NC + c] + 1e-5);
        double sh1 = (double)b1[s*NC + c] - (double)m1[s*NC + c] * sc1;
        double A   = (double)w1[s*NC + c] * sc1;
        sAf[c]  = (float)A;
        sBf[c]  = (float)sh1;
        scls[c] = (A > 0.0) ? 1 : (A < 0.0) ? 2 : (sh1 > 0.0) ? 3 : 0;
        sthv[c] = (A != 0.0) ? (float)(-sh1 / A) : CUDART_INF_F;
        sidx[c] = c;
    }
    __syncthreads();

    // bitonic sort of 64 (key sthv, payload sidx)
    for (int ksz = 2; ksz <= 64; ksz <<= 1) {
        for (int j = ksz >> 1; j > 0; j >>= 1) {
            int ixj = c ^ j;
            if (ixj > c) {
                float a = sthv[c], bb = sthv[ixj];
                int   ia = sidx[c], ib = sidx[ixj];
                bool  up = ((c & ksz) == 0);
                if (up ? (a > bb) : (a < bb)) {
                    sthv[c] = bb; sthv[ixj] = a;
                    sidx[c] = ib; sidx[ixj] = ia;
                }
            }
            __syncthreads();
        }
    }

    srk[sidx[c]] = c;
    if (k == 0) {
        g_th[s][c] = sthv[c];
        if (c == 0) {
            g_wv[s][0] = lp[s*2]; g_wv[s][1] = lp[s*2+1];
            g_wv[s][2] = hp[s*2]; g_wv[s][3] = hp[s*2+1];
        }
    }
    __syncthreads();

    // entry (s, k, o = c): fp32 masked sums, 4 independent chains
    const int o = c;
    const double sc2 = (double)g2[s*NC + o] / sqrt((double)v2[s*NC + o] + 1e-5);
    const double sh2 = (double)b2[s*NC + o] - (double)m2[s*NC + o] * sc2;

    float s1a = 0.f, s2a = 0.f, s1b = 0.f, s2b = 0.f;
    float s1c = 0.f, s2c = 0.f, s1d = 0.f, s2d = 0.f;
    #pragma unroll
    for (int cc = 0; cc < 64; cc += 4) {
        #define ACC(CI, S1, S2)                                          \
        {   const int cl = scls[CI];                                     \
            const bool act = (cl == 1) ? (srk[CI] < k)                   \
                           : (cl == 2) ? (srk[CI] >= k)                  \
                                       : (cl == 3);                      \
            if (act) {                                                   \
                const float w = sw2[o*65 + (CI)];                        \
                S1 = fmaf(w, sBf[CI], S1);                               \
                S2 = fmaf(w, sAf[CI], S2);                               \
            }                                                            \
        }
        ACC(cc + 0, s1a, s2a)
        ACC(cc + 1, s1b, s2b)
        ACC(cc + 2, s1c, s2c)
        ACC(cc + 3, s1d, s2d)
        #undef ACC
    }
    const double s1 = (double)((s1a + s1b) + (s1c + s1d));
    const double s2 = (double)((s2a + s2b) + (s2c + s2d));
    g_tab[s][k][o] = make_float2((float)(sc2*s1 + sh2), (float)(sc2*s2));
}

// ---------------------------------------------------------------------------
// Main kernel (R13 + 16-way replicated thresholds for the rank search):
// grid (30, 40), thread owns 4 consecutive pixels; streaming STG.128 via
// per-plane shift d = o & 3 with a 7-slot (3 halo + 4 own) shfl window.
// smem: 33,800 (table) + 4,096 (replicated thresholds) = 37,896 B -> still
// 6 blocks/SM (228 KB carveout), no occupancy change.
// ---------------------------------------------------------------------------
__global__ void __launch_bounds__(256)
dwt_pwl_kernel(const float* __restrict__ x, float* __restrict__ out)
{
    __shared__ float2 stab[65 * 65];     // idx = k*65 + o  (padded stride)
    __shared__ float  sthr[64 * 16];     // thresholds, 16 replicas: [idx*16+rep]

    const int sb = blockIdx.y;          // 0..39
    const int s  = sb / NB;
    const int b  = sb - s * NB;

    const float2* gt = &g_tab[s][0][0];
    for (int i = threadIdx.x; i < 65 * 64; i += 256) {
        int k = i >> 6, o = i & 63;
        stab[k * 65 + o] = gt[i];
    }
    for (int i = threadIdx.x; i < 64 * 16; i += 256)
        sthr[i] = g_th[s][i >> 4];
    __syncthreads();

    const float lp0 = g_wv[s][0], lp1 = g_wv[s][1];
    const float hp0 = g_wv[s][2], hp1 = g_wv[s][3];

    const float* __restrict__ xb = x + (size_t)b * HIN * WIN;
    float* __restrict__ outL = out + (size_t)sb * NPIX;
    float* __restrict__ outH = out + (size_t)(NS*NB + sb) * NPIX;
    float* __restrict__ outP = out + (size_t)2*NS*NB*NPIX + (size_t)sb * NC * NPIX;

    const int lane = threadIdx.x & 31;
    const int rep  = lane & 15;          // this lane's threshold replica
    const int gstride = gridDim.x * blockDim.x;

    // rank via binary search in this lane's replica (bank spread: <=2 lanes/bank)
    auto rankOf = [&](float L) -> int {
        const float* th = sthr + rep;
        int kk = (th[31*16]        < L) ? 32 : 0;
        kk += (th[(kk + 15)*16] < L) ? 16 : 0;
        kk += (th[(kk +  7)*16] < L) ?  8 : 0;
        kk += (th[(kk +  3)*16] < L) ?  4 : 0;
        kk += (th[(kk +  1)*16] < L) ?  2 : 0;
        kk += (th[kk*16]        < L) ?  1 : 0;
        return kk;
    };

    // compute L, Hc, rank k for one pixel (fully guarded, incl. bottom row)
    auto pixLHK = [&](int pix, float& L, float& H, int& k) {
        L = 0.f; H = 0.f;
        if (pix >= 0 && pix < NPIX) {
            unsigned up = (unsigned)pix;
            int i = up / WO;
            int j = up - i * WO;
            int r0 = 2*i - 1, r1 = 2*i;
            int c0 = 2*j - 1, c1 = 2*j;
            float x00 = (r0 >= 0  && c0 >= 0 ) ? xb[r0*WIN + c0] : 0.f;
            float x01 = (r0 >= 0  && c1 < WIN) ? xb[r0*WIN + c1] : 0.f;
            float x10 = (r1 < HIN && c0 >= 0 ) ? xb[r1*WIN + c0] : 0.f;
            float x11 = (r1 < HIN && c1 < WIN) ? xb[r1*WIN + c1] : 0.f;
            L = lp0*(lp0*x00 + lp1*x01) + lp1*(lp0*x10 + lp1*x11);
            H = hp0*(hp0*x00 + hp1*x01) + hp1*(hp0*x10 + hp1*x11);
        }
        k = rankOf(L);
    };

    for (int gw = blockIdx.x * 256 + (int)(threadIdx.x & ~31u); gw < NGRP;
         gw += gstride)
    {
        const int g = gw + lane;
        const int pix0 = 4 * g;

        float Ls[7], Hs[7]; int ks[7];
        pixLHK(pix0 + 0, Ls[3], Hs[3], ks[3]);
        pixLHK(pix0 + 1, Ls[4], Hs[4], ks[4]);
        pixLHK(pix0 + 2, Ls[5], Hs[5], ks[5]);
        pixLHK(pix0 + 3, Ls[6], Hs[6], ks[6]);

        // halo (previous group's pixels 1..3) via shfl; lane 0 recomputes
        Ls[0] = __shfl_up_sync(0xffffffffu, Ls[4], 1);
        Ls[1] = __shfl_up_sync(0xffffffffu, Ls[5], 1);
        Ls[2] = __shfl_up_sync(0xffffffffu, Ls[6], 1);
        Hs[0] = __shfl_up_sync(0xffffffffu, Hs[4], 1);
        Hs[1] = __shfl_up_sync(0xffffffffu, Hs[5], 1);
        Hs[2] = __shfl_up_sync(0xffffffffu, Hs[6], 1);
        ks[0] = __shfl_up_sync(0xffffffffu, ks[4], 1);
        ks[1] = __shfl_up_sync(0xffffffffu, ks[5], 1);
        ks[2] = __shfl_up_sync(0xffffffffu, ks[6], 1);
        if (lane == 0) {
            pixLHK(pix0 - 3, Ls[0], Hs[0], ks[0]);
            pixLHK(pix0 - 2, Ls[1], Hs[1], ks[1]);
            pixLHK(pix0 - 1, Ls[2], Hs[2], ks[2]);
        }

        if (g >= NGRP) continue;

        const bool edge = (g == 0) || (g == NGRP - 1);

        if (!edge) {
            // ---- P planes: 16 quads of 4 channels, one streaming STG.128 ----
            float* bp = outP + pix0;
            #pragma unroll
            for (int q = 0; q < 16; q++) {
                const int o0 = 4 * q;
                {   // o0, d=0: slots 3..6, addr +0
                    float2 f0 = stab[ks[3]*65 + o0], f1 = stab[ks[4]*65 + o0];
                    float2 f2 = stab[ks[5]*65 + o0], f3 = stab[ks[6]*65 + o0];
                    float4 v = make_float4(fmaxf(fmaf(f0.y, Ls[3], f0.x), 0.f),
                                           fmaxf(fmaf(f1.y, Ls[4], f1.x), 0.f),
                                           fmaxf(fmaf(f2.y, Ls[5], f2.x), 0.f),
                                           fmaxf(fmaf(f3.y, Ls[6], f3.x), 0.f));
                    __stcs(reinterpret_cast<float4*>(bp), v);
                }
                {   // o0+1, d=1: slots 2..5, addr +NPIX-1
                    float2 f0 = stab[ks[2]*65 + o0+1], f1 = stab[ks[3]*65 + o0+1];
                    float2 f2 = stab[ks[4]*65 + o0+1], f3 = stab[ks[5]*65 + o0+1];
                    float4 v = make_float4(fmaxf(fmaf(f0.y, Ls[2], f0.x), 0.f),
                                           fmaxf(fmaf(f1.y, Ls[3], f1.x), 0.f),
                                           fmaxf(fmaf(f2.y, Ls[4], f2.x), 0.f),
                                           fmaxf(fmaf(f3.y, Ls[5], f3.x), 0.f));
                    __stcs(reinterpret_cast<float4*>(bp + (NPIX - 1)), v);
                }
                {   // o0+2, d=2: slots 1..4, addr +2*NPIX-2
                    float2 f0 = stab[ks[1]*65 + o0+2], f1 = stab[ks[2]*65 + o0+2];
                    float2 f2 = stab[ks[3]*65 + o0+2], f3 = stab[ks[4]*65 + o0+2];
                    float4 v = make_float4(fmaxf(fmaf(f0.y, Ls[1], f0.x), 0.f),
                                           fmaxf(fmaf(f1.y, Ls[2], f1.x), 0.f),
                                           fmaxf(fmaf(f2.y, Ls[3], f2.x), 0.f),
                                           fmaxf(fmaf(f3.y, Ls[4], f3.x), 0.f));
                    __stcs(reinterpret_cast<float4*>(bp + (2*NPIX - 2)), v);
                }
                {   // o0+3, d=3: slots 0..3, addr +3*NPIX-3
                    float2 f0 = stab[ks[0]*65 + o0+3], f1 = stab[ks[1]*65 + o0+3];
                    float2 f2 = stab[ks[2]*65 + o0+3], f3 = stab[ks[3]*65 + o0+3];
                    float4 v = make_float4(fmaxf(fmaf(f0.y, Ls[0], f0.x), 0.f),
                                           fmaxf(fmaf(f1.y, Ls[1], f1.x), 0.f),
                                           fmaxf(fmaf(f2.y, Ls[2], f2.x), 0.f),
                                           fmaxf(fmaf(f3.y, Ls[3], f3.x), 0.f));
                    __stcs(reinterpret_cast<float4*>(bp + (3*NPIX - 3)), v);
                }
                bp += (size_t)4 * NPIX;
            }

            // ---- L / Hc planes: runtime shift (uniform per block) ----
            switch (sb & 3) {
            case 0:
                __stcs(reinterpret_cast<float4*>(outL + pix0),
                       make_float4(Ls[3], Ls[4], Ls[5], Ls[6]));
                __stcs(reinterpret_cast<float4*>(outH + pix0),
                       make_float4(Hs[3], Hs[4], Hs[5], Hs[6]));
                break;
            case 1:
                __stcs(reinterpret_cast<float4*>(outL + pix0 - 1),
                       make_float4(Ls[2], Ls[3], Ls[4], Ls[5]));
                __stcs(reinterpret_cast<float4*>(outH + pix0 - 1),
                       make_float4(Hs[2], Hs[3], Hs[4], Hs[5]));
                break;
            case 2:
                __stcs(reinterpret_cast<float4*>(outL + pix0 - 2),
                       make_float4(Ls[1], Ls[2], Ls[3], Ls[4]));
                __stcs(reinterpret_cast<float4*>(outH + pix0 - 2),
                       make_float4(Hs[1], Hs[2], Hs[3], Hs[4]));
                break;
            default:
                __stcs(reinterpret_cast<float4*>(outL + pix0 - 3),
                       make_float4(Ls[0], Ls[1], Ls[2], Ls[3]));
                __stcs(reinterpret_cast<float4*>(outH + pix0 - 3),
                       make_float4(Hs[0], Hs[1], Hs[2], Hs[3]));
                break;
            }
        } else {
            // ---- edge groups (first/last of plane): masked scalar stores ----
            #pragma unroll 4
            for (int o = 0; o < 64; o++) {
                const int d = o & 3;
                #pragma unroll
                for (int e = 0; e < 4; e++) {
                    int pix = pix0 - d + e;
                    if (pix >= 0 && pix < NPIX) {
                        float2 f = stab[ks[3 - d + e] * 65 + o];
                        outP[(size_t)o * NPIX + pix] =
                            fmaxf(fmaf(f.y, Ls[3 - d + e], f.x), 0.f);
                    }
                }
            }
            switch (sb & 3) {
            #define EDGE_LH(D)                                              \
                { _Pragma("unroll")                                         \
                  for (int e = 0; e < 4; e++) {                             \
                      int pix = pix0 - (D) + e;                             \
                      if (pix >= 0 && pix < NPIX) {                         \
                          outL[pix] = Ls[3 - (D) + e];                      \
                          outH[pix] = Hs[3 - (D) + e];                      \
                      }                                                     \
                  } }
            case 0:  EDGE_LH(0) break;
            case 1:  EDGE_LH(1) break;
            case 2:  EDGE_LH(2) break;
            default: EDGE_LH(3) break;
            #undef EDGE_LH
            }
        }
    }
}

// ---------------------------------------------------------------------------
extern "C" void kernel_launch(void* const* d_in, const int* in_sizes, int n_in,
                              void* d_out, int out_size)
{
    const float* x  = (const float*)d_in[0];
    const float* lp = (const float*)d_in[1];
    const float* hp = (const float*)d_in[2];
    const float* w1 = (const float*)d_in[3];
    const float* w2 = (const float*)d_in[4];
    const float* g1 = (const float*)d_in[5];
    const float* b1 = (const float*)d_in[6];
    const float* m1 = (const float*)d_in[7];
    const float* v1 = (const float*)d_in[8];
    const float* g2 = (const float*)d_in[9];
    const float* b2 = (const float*)d_in[10];
    const float* m2 = (const float*)d_in[11];
    const float* v2 = (const float*)d_in[12];
    float* out = (float*)d_out;

    precompute_tab<<<dim3(65, NS), 64>>>(lp, hp, w1, w2, g1, b1, m1, v1,
                                         g2, b2, m2, v2);

    dim3 grid(30, NS * NB);   // 1200 blocks — best-measured main config
    dwt_pwl_kernel<<<grid, 256>>>(x, out);
}

// round 15
// speedup vs baseline: 1.2543x; 1.0272x over previous
#include <cuda_runtime.h>
#include <math_constants.h>

#define NS   5
#define NC   64
#define NB   8
#define HIN  512
#define WIN  512
#define HO   257
#define WO   257
#define NPIX (HO*WO)            // 66049
#define NGRP ((NPIX + 3) / 4)   // 16513 groups of 4 pixels

// Piecewise-linear table, k-major, float2 {S1,S2}:
//   P[o](L) = max(S1 + S2*L, 0), k = #{sorted thresholds < L}
__device__ float2 g_tab[NS][65][NC];
__device__ float  g_th [NS][64];
__device__ float  g_wv [NS][4];

// ---------------------------------------------------------------------------
// Precompute (R10-R14 verbatim — measured-best): grid (65, 5) x 64.
// fp64 channel meta + bitonic sort (exact k-bucketing); w2 staged via
// LDG.128; table sums in fp32 with 4 independent split accumulators.
// ---------------------------------------------------------------------------
__global__ void __launch_bounds__(64)
precompute_tab(
    const float* __restrict__ lp, const float* __restrict__ hp,
    const float* __restrict__ w1, const float* __restrict__ w2,
    const float* __restrict__ g1, const float* __restrict__ b1,
    const float* __restrict__ m1, const float* __restrict__ v1,
    const float* __restrict__ g2, const float* __restrict__ b2,
    const float* __restrict__ m2, const float* __restrict__ v2)
{
    const int s = blockIdx.y;
    const int k = blockIdx.x;       // 0..64
    const int c = threadIdx.x;      // 0..63

    __shared__ float  sw2[64 * 65];   // padded stride 65: conflict-free columns
    __shared__ float  sAf[64], sBf[64];
    __shared__ float  sthv[64];
    __shared__ int    sidx[64];
    __shared__ int    srk [64];
    __shared__ signed char scls[64];  // 1: A>0, 2: A<0, 3: A==0 && B>0, 0: dead

    // stage w2 with vector loads: 16 LDG.128 per thread
    {
        const float4* w2v = reinterpret_cast<const float4*>(w2) + s * 1024;
        #pragma unroll
        for (int t = 0; t < 16; t++) {
            const int i   = c + t * 64;       // float4 index 0..1023
            const float4 v = w2v[i];
            const int row = i >> 4;           // 16 float4 per row
            const int col = (i & 15) * 4;
            float* dst = &sw2[row * 65 + col];
            dst[0] = v.x; dst[1] = v.y; dst[2] = v.z; dst[3] = v.w;
        }
    }

    // per-channel meta in fp64 (k-bucketing identical to prior rounds)
    {
        double sc1 = (double)g1[s*NC + c] / sqrt((double)v1[s*NC + c] + 1e-5);
        double sh1 = (double)b1[s*NC + c] - (double)m1[s*NC + c] * sc1;
        double A   = (double)w1[s*NC + c] * sc1;
        sAf[c]  = (float)A;
        sBf[c]  = (float)sh1;
        scls[c] = (A > 0.0) ? 1 : (A < 0.0) ? 2 : (sh1 > 0.0) ? 3 : 0;
        sthv[c] = (A != 0.0) ? (float)(-sh1 / A) : CUDART_INF_F;
        sidx[c] = c;
    }
    __syncthreads();

    // bitonic sort of 64 (key sthv, payload sidx)
    for (int ksz = 2; ksz <= 64; ksz <<= 1) {
        for (int j = ksz >> 1; j > 0; j >>= 1) {
            int ixj = c ^ j;
            if (ixj > c) {
                float a = sthv[c], bb = sthv[ixj];
                int   ia = sidx[c], ib = sidx[ixj];
                bool  up = ((c & ksz) == 0);
                if (up ? (a > bb) : (a < bb)) {
                    sthv[c] = bb; sthv[ixj] = a;
                    sidx[c] = ib; sidx[ixj] = ia;
                }
            }
            __syncthreads();
        }
    }

    srk[sidx[c]] = c;
    if (k == 0) {
        g_th[s][c] = sthv[c];
        if (c == 0) {
            g_wv[s][0] = lp[s*2]; g_wv[s][1] = lp[s*2+1];
            g_wv[s][2] = hp[s*2]; g_wv[s][3] = hp[s*2+1];
        }
    }
    __syncthreads();

    // entry (s, k, o = c): fp32 masked sums, 4 independent chains
    const int o = c;
    const double sc2 = (double)g2[s*NC + o] / sqrt((double)v2[s*NC + o] + 1e-5);
    const double sh2 = (double)b2[s*NC + o] - (double)m2[s*NC + o] * sc2;

    float s1a = 0.f, s2a = 0.f, s1b = 0.f, s2b = 0.f;
    float s1c = 0.f, s2c = 0.f, s1d = 0.f, s2d = 0.f;
    #pragma unroll
    for (int cc = 0; cc < 64; cc += 4) {
        #define ACC(CI, S1, S2)                                          \
        {   const int cl = scls[CI];                                     \
            const bool act = (cl == 1) ? (srk[CI] < k)                   \
                           : (cl == 2) ? (srk[CI] >= k)                  \
                                       : (cl == 3);                      \
            if (act) {                                                   \
                const float w = sw2[o*65 + (CI)];                        \
                S1 = fmaf(w, sBf[CI], S1);                               \
                S2 = fmaf(w, sAf[CI], S2);                               \
            }                                                            \
        }
        ACC(cc + 0, s1a, s2a)
        ACC(cc + 1, s1b, s2b)
        ACC(cc + 2, s1c, s2c)
        ACC(cc + 3, s1d, s2d)
        #undef ACC
    }
    const double s1 = (double)((s1a + s1b) + (s1c + s1d));
    const double s2 = (double)((s2a + s2b) + (s2c + s2d));
    g_tab[s][k][o] = make_float2((float)(sc2*s1 + sh2), (float)(sc2*s2));
}

// ---------------------------------------------------------------------------
// Main kernel (final configuration — measured-best total): grid (30, 40),
// thread owns 4 consecutive pixels; streaming STG.128 via per-plane shift
// d = o & 3 with a 7-slot (3 halo + 4 own) shfl window; 16-way replicated
// thresholds for the rank binary search.
// ---------------------------------------------------------------------------
__global__ void __launch_bounds__(256)
dwt_pwl_kernel(const float* __restrict__ x, float* __restrict__ out)
{
    __shared__ float2 stab[65 * 65];     // idx = k*65 + o  (padded stride)
    __shared__ float  sthr[64 * 16];     // thresholds, 16 replicas: [idx*16+rep]

    const int sb = blockIdx.y;          // 0..39
    const int s  = sb / NB;
    const int b  = sb - s * NB;

    const float2* gt = &g_tab[s][0][0];
    for (int i = threadIdx.x; i < 65 * 64; i += 256) {
        int k = i >> 6, o = i & 63;
        stab[k * 65 + o] = gt[i];
    }
    for (int i = threadIdx.x; i < 64 * 16; i += 256)
        sthr[i] = g_th[s][i >> 4];
    __syncthreads();

    const float lp0 = g_wv[s][0], lp1 = g_wv[s][1];
    const float hp0 = g_wv[s][2], hp1 = g_wv[s][3];

    const float* __restrict__ xb = x + (size_t)b * HIN * WIN;
    float* __restrict__ outL = out + (size_t)sb * NPIX;
    float* __restrict__ outH = out + (size_t)(NS*NB + sb) * NPIX;
    float* __restrict__ outP = out + (size_t)2*NS*NB*NPIX + (size_t)sb * NC * NPIX;

    const int lane = threadIdx.x & 31;
    const int rep  = lane & 15;          // this lane's threshold replica
    const int gstride = gridDim.x * blockDim.x;

    // rank via binary search in this lane's replica (bank spread: <=2 lanes/bank)
    auto rankOf = [&](float L) -> int {
        const float* th = sthr + rep;
        int kk = (th[31*16]        < L) ? 32 : 0;
        kk += (th[(kk + 15)*16] < L) ? 16 : 0;
        kk += (th[(kk +  7)*16] < L) ?  8 : 0;
        kk += (th[(kk +  3)*16] < L) ?  4 : 0;
        kk += (th[(kk +  1)*16] < L) ?  2 : 0;
        kk += (th[kk*16]        < L) ?  1 : 0;
        return kk;
    };

    // compute L, Hc, rank k for one pixel (fully guarded, incl. bottom row)
    auto pixLHK = [&](int pix, float& L, float& H, int& k) {
        L = 0.f; H = 0.f;
        if (pix >= 0 && pix < NPIX) {
            unsigned up = (unsigned)pix;
            int i = up / WO;
            int j = up - i * WO;
            int r0 = 2*i - 1, r1 = 2*i;
            int c0 = 2*j - 1, c1 = 2*j;
            float x00 = (r0 >= 0  && c0 >= 0 ) ? xb[r0*WIN + c0] : 0.f;
            float x01 = (r0 >= 0  && c1 < WIN) ? xb[r0*WIN + c1] : 0.f;
            float x10 = (r1 < HIN && c0 >= 0 ) ? xb[r1*WIN + c0] : 0.f;
            float x11 = (r1 < HIN && c1 < WIN) ? xb[r1*WIN + c1] : 0.f;
            L = lp0*(lp0*x00 + lp1*x01) + lp1*(lp0*x10 + lp1*x11);
            H = hp0*(hp0*x00 + hp1*x01) + hp1*(hp0*x10 + hp1*x11);
        }
        k = rankOf(L);
    };

    for (int gw = blockIdx.x * 256 + (int)(threadIdx.x & ~31u); gw < NGRP;
         gw += gstride)
    {
        const int g = gw + lane;
        const int pix0 = 4 * g;

        float Ls[7], Hs[7]; int ks[7];
        pixLHK(pix0 + 0, Ls[3], Hs[3], ks[3]);
        pixLHK(pix0 + 1, Ls[4], Hs[4], ks[4]);
        pixLHK(pix0 + 2, Ls[5], Hs[5], ks[5]);
        pixLHK(pix0 + 3, Ls[6], Hs[6], ks[6]);

        // halo (previous group's pixels 1..3) via shfl; lane 0 recomputes
        Ls[0] = __shfl_up_sync(0xffffffffu, Ls[4], 1);
        Ls[1] = __shfl_up_sync(0xffffffffu, Ls[5], 1);
        Ls[2] = __shfl_up_sync(0xffffffffu, Ls[6], 1);
        Hs[0] = __shfl_up_sync(0xffffffffu, Hs[4], 1);
        Hs[1] = __shfl_up_sync(0xffffffffu, Hs[5], 1);
        Hs[2] = __shfl_up_sync(0xffffffffu, Hs[6], 1);
        ks[0] = __shfl_up_sync(0xffffffffu, ks[4], 1);
        ks[1] = __shfl_up_sync(0xffffffffu, ks[5], 1);
        ks[2] = __shfl_up_sync(0xffffffffu, ks[6], 1);
        if (lane == 0) {
            pixLHK(pix0 - 3, Ls[0], Hs[0], ks[0]);
            pixLHK(pix0 - 2, Ls[1], Hs[1], ks[1]);
            pixLHK(pix0 - 1, Ls[2], Hs[2], ks[2]);
        }

        if (g >= NGRP) continue;

        const bool edge = (g == 0) || (g == NGRP - 1);

        if (!edge) {
            // ---- P planes: 16 quads of 4 channels, one streaming STG.128 ----
            float* bp = outP + pix0;
            #pragma unroll
            for (int q = 0; q < 16; q++) {
                const int o0 = 4 * q;
                {   // o0, d=0: slots 3..6, addr +0
                    float2 f0 = stab[ks[3]*65 + o0], f1 = stab[ks[4]*65 + o0];
                    float2 f2 = stab[ks[5]*65 + o0], f3 = stab[ks[6]*65 + o0];
                    float4 v = make_float4(fmaxf(fmaf(f0.y, Ls[3], f0.x), 0.f),
                                           fmaxf(fmaf(f1.y, Ls[4], f1.x), 0.f),
                                           fmaxf(fmaf(f2.y, Ls[5], f2.x), 0.f),
                                           fmaxf(fmaf(f3.y, Ls[6], f3.x), 0.f));
                    __stcs(reinterpret_cast<float4*>(bp), v);
                }
                {   // o0+1, d=1: slots 2..5, addr +NPIX-1
                    float2 f0 = stab[ks[2]*65 + o0+1], f1 = stab[ks[3]*65 + o0+1];
                    float2 f2 = stab[ks[4]*65 + o0+1], f3 = stab[ks[5]*65 + o0+1];
                    float4 v = make_float4(fmaxf(fmaf(f0.y, Ls[2], f0.x), 0.f),
                                           fmaxf(fmaf(f1.y, Ls[3], f1.x), 0.f),
                                           fmaxf(fmaf(f2.y, Ls[4], f2.x), 0.f),
                                           fmaxf(fmaf(f3.y, Ls[5], f3.x), 0.f));
                    __stcs(reinterpret_cast<float4*>(bp + (NPIX - 1)), v);
                }
                {   // o0+2, d=2: slots 1..4, addr +2*NPIX-2
                    float2 f0 = stab[ks[1]*65 + o0+2], f1 = stab[ks[2]*65 + o0+2];
                    float2 f2 = stab[ks[3]*65 + o0+2], f3 = stab[ks[4]*65 + o0+2];
                    float4 v = make_float4(fmaxf(fmaf(f0.y, Ls[1], f0.x), 0.f),
                                           fmaxf(fmaf(f1.y, Ls[2], f1.x), 0.f),
                                           fmaxf(fmaf(f2.y, Ls[3], f2.x), 0.f),
                                           fmaxf(fmaf(f3.y, Ls[4], f3.x), 0.f));
                    __stcs(reinterpret_cast<float4*>(bp + (2*NPIX - 2)), v);
                }
                {   // o0+3, d=3: slots 0..3, addr +3*NPIX-3
                    float2 f0 = stab[ks[0]*65 + o0+3], f1 = stab[ks[1]*65 + o0+3];
                    float2 f2 = stab[ks[2]*65 + o0+3], f3 = stab[ks[3]*65 + o0+3];
                    float4 v = make_float4(fmaxf(fmaf(f0.y, Ls[0], f0.x), 0.f),
                                           fmaxf(fmaf(f1.y, Ls[1], f1.x), 0.f),
                                           fmaxf(fmaf(f2.y, Ls[2], f2.x), 0.f),
                                           fmaxf(fmaf(f3.y, Ls[3], f3.x), 0.f));
                    __stcs(reinterpret_cast<float4*>(bp + (3*NPIX - 3)), v);
                }
                bp += (size_t)4 * NPIX;
            }

            // ---- L / Hc planes: runtime shift (uniform per block) ----
            switch (sb & 3) {
            case 0:
                __stcs(reinterpret_cast<float4*>(outL + pix0),
                       make_float4(Ls[3], Ls[4], Ls[5], Ls[6]));
                __stcs(reinterpret_cast<float4*>(outH + pix0),
                       make_float4(Hs[3], Hs[4], Hs[5], Hs[6]));
                break;
            case 1:
                __stcs(reinterpret_cast<float4*>(outL + pix0 - 1),
                       make_float4(Ls[2], Ls[3], Ls[4], Ls[5]));
                __stcs(reinterpret_cast<float4*>(outH + pix0 - 1),
                       make_float4(Hs[2], Hs[3], Hs[4], Hs[5]));
                break;
            case 2:
                __stcs(reinterpret_cast<float4*>(outL + pix0 - 2),
                       make_float4(Ls[1], Ls[2], Ls[3], Ls[4]));
                __stcs(reinterpret_cast<float4*>(outH + pix0 - 2),
                       make_float4(Hs[1], Hs[2], Hs[3], Hs[4]));
                break;
            default:
                __stcs(reinterpret_cast<float4*>(outL + pix0 - 3),
                       make_float4(Ls[0], Ls[1], Ls[2], Ls[3]));
                __stcs(reinterpret_cast<float4*>(outH + pix0 - 3),
                       make_float4(Hs[0], Hs[1], Hs[2], Hs[3]));
                break;
            }
        } else {
            // ---- edge groups (first/last of plane): masked streaming stores ----
            #pragma unroll 4
            for (int o = 0; o < 64; o++) {
                const int d = o & 3;
                #pragma unroll
                for (int e = 0; e < 4; e++) {
                    int pix = pix0 - d + e;
                    if (pix >= 0 && pix < NPIX) {
                        float2 f = stab[ks[3 - d + e] * 65 + o];
                        __stcs(&outP[(size_t)o * NPIX + pix],
                               fmaxf(fmaf(f.y, Ls[3 - d + e], f.x), 0.f));
                    }
                }
            }
            switch (sb & 3) {
            #define EDGE_LH(D)                                              \
                { _Pragma("unroll")                                         \
                  for (int e = 0; e < 4; e++) {                             \
                      int pix = pix0 - (D) + e;                             \
                      if (pix >= 0 && pix < NPIX) {                         \
                          __stcs(&outL[pix], Ls[3 - (D) + e]);              \
                          __stcs(&outH[pix], Hs[3 - (D) + e]);              \
                      }                                                     \
                  } }
            case 0:  EDGE_LH(0) break;
            case 1:  EDGE_LH(1) break;
            case 2:  EDGE_LH(2) break;
            default: EDGE_LH(3) break;
            #undef EDGE_LH
            }
        }
    }
}

// ---------------------------------------------------------------------------
extern "C" void kernel_launch(void* const* d_in, const int* in_sizes, int n_in,
                              void* d_out, int out_size)
{
    const float* x  = (const float*)d_in[0];
    const float* lp = (const float*)d_in[1];
    const float* hp = (const float*)d_in[2];
    const float* w1 = (const float*)d_in[3];
    const float* w2 = (const float*)d_in[4];
    const float* g1 = (const float*)d_in[5];
    const float* b1 = (const float*)d_in[6];
    const float* m1 = (const float*)d_in[7];
    const float* v1 = (const float*)d_in[8];
    const float* g2 = (const float*)d_in[9];
    const float* b2 = (const float*)d_in[10];
    const float* m2 = (const float*)d_in[11];
    const float* v2 = (const float*)d_in[12];
    float* out = (float*)d_out;

    precompute_tab<<<dim3(65, NS), 64>>>(lp, hp, w1, w2, g1, b1, m1, v1,
                                         g2, b2, m2, v2);

    dim3 grid(30, NS * NB);   // 1200 blocks — best-measured main config
    dwt_pwl_kernel<<<grid, 256>>>(x, out);
}